// round 12
// baseline (speedup 1.0000x reference)
#include <cuda_runtime.h>
#include <cuda_fp16.h>
#include <stdint.h>

// ---------------------------------------------------------------------------
// SNN: pool -> fc_in -> 3x LIF layers -> readout, T=8.
// Split-precision fp16 HMMA (mma.sync.m16n8k16), exact for spikes,
// <=2^-22 relative residual for weights (hi+lo split, scale 32).
// R12: GEMM2 -> 256x128 CTA tile / 64x64 warp tile at occ 1 (255 regs),
// halving ldsm bytes per MAC. GEMM1/GEMM3 = exact R9 configs.
// ---------------------------------------------------------------------------

#define T_STEPS 8
#define BB      32
#define CC      4
#define CHUNK   29
#define HH      64
#define WW      64
#define TPP     14
#define HP      32
#define WP      32
#define RR      56
#define D_INF   1024
#define H0F     2048
#define H1F     2048
#define H2F     1024
#define NCLS    4
#define MS      (BB*RR)         // 1792
#define M_ALL   (T_STEPS*MS)    // 14336
#define FOUT    (RR*H2F)        // 57344

#define SCALE_W 32.0f
#define INV_SW  (1.0f/32.0f)

#define BKT   32
#define PITCH 80                     // bytes per 64B k-chunk row (padded)

// ------------------------- static scratch ----------------------------------
__device__ __half g_feat_h[(size_t)M_ALL * D_INF];
__device__ __half g_feat_l[(size_t)M_ALL * D_INF];
__device__ float  g_curin [(size_t)M_ALL * H0F];
__device__ __half g_spkin_h[(size_t)MS * H0F];
__device__ float  g_m_in  [(size_t)MS * H0F];
__device__ __half g_spk1_h[(size_t)MS * H1F];
__device__ float  g_m_h1  [(size_t)MS * H1F];
__device__ float  g_spk2  [(size_t)MS * H2F];
__device__ float  g_m_h2  [(size_t)MS * H2F];
__device__ float  g_m_out [BB * NCLS];
__device__ __half g_Win_h[(size_t)H0F * D_INF];
__device__ __half g_Win_l[(size_t)H0F * D_INF];
__device__ __half g_Wh1_h[(size_t)H1F * H0F];
__device__ __half g_Wh1_l[(size_t)H1F * H0F];
__device__ __half g_Wh2_h[(size_t)H2F * H1F];
__device__ __half g_Wh2_l[(size_t)H2F * H1F];

__device__ __forceinline__ float clamp01(float v) {
    return fminf(fmaxf(v, 0.0f), 1.0f);
}
__device__ __forceinline__ uint32_t smem_u32(const void* p) {
    uint32_t a;
    asm("{ .reg .u64 t; cvta.to.shared.u64 t, %1; cvt.u32.u64 %0, t; }" : "=r"(a) : "l"(p));
    return a;
}
__device__ __forceinline__ void cp_async16(uint32_t dst, const void* src) {
    asm volatile("cp.async.cg.shared.global [%0], [%1], 16;" :: "r"(dst), "l"(src));
}
__device__ __forceinline__ void ldmx4(uint32_t* r, uint32_t addr) {
    asm volatile("ldmatrix.sync.aligned.m8n8.x4.shared.b16 {%0,%1,%2,%3}, [%4];"
        : "=r"(r[0]), "=r"(r[1]), "=r"(r[2]), "=r"(r[3]) : "r"(addr));
}
__device__ __forceinline__ void mma16816(float* c, const uint32_t* a,
                                         uint32_t b0, uint32_t b1) {
    asm volatile(
        "mma.sync.aligned.m16n8k16.row.col.f32.f16.f16.f32 "
        "{%0,%1,%2,%3}, {%4,%5,%6,%7}, {%8,%9}, {%0,%1,%2,%3};"
        : "+f"(c[0]), "+f"(c[1]), "+f"(c[2]), "+f"(c[3])
        : "r"(a[0]), "r"(a[1]), "r"(a[2]), "r"(a[3]), "r"(b0), "r"(b1));
}

// ------------------------------ zero membranes ------------------------------
__global__ void zero_kernel() {
    int i = blockIdx.x * blockDim.x + threadIdx.x;
    int stride = gridDim.x * blockDim.x;
    for (int k = i; k < MS * H0F; k += stride) { g_m_in[k] = 0.f; g_m_h1[k] = 0.f; }
    for (int k = i; k < MS * H2F; k += stride) g_m_h2[k] = 0.f;
    if (i < BB * NCLS) g_m_out[i] = 0.f;
}

// ------------------------- weight split + transpose -------------------------
__global__ void split_tr_kernel(const float* __restrict__ W,
                                __half* __restrict__ Th, __half* __restrict__ Tl,
                                int K, int N) {
    __shared__ float tile[32][33];
    int n0 = blockIdx.x * 32, k0 = blockIdx.y * 32;
    int tx = threadIdx.x, ty = threadIdx.y;   // 32 x 8
#pragma unroll
    for (int j = 0; j < 32; j += 8)
        tile[ty + j][tx] = W[(size_t)(k0 + ty + j) * N + n0 + tx];
    __syncthreads();
#pragma unroll
    for (int j = 0; j < 32; j += 8) {
        float w = tile[tx][ty + j] * SCALE_W;
        __half hi = __float2half_rn(w);
        __half lo = __float2half_rn(w - __half2float(hi));
        size_t o = (size_t)(n0 + ty + j) * K + k0 + tx;
        Th[o] = hi; Tl[o] = lo;
    }
}

// ------------------------------- avg pool 3d --------------------------------
__global__ void pool_kernel(const float* __restrict__ x) {
    int blk = blockIdx.x;
    int tp = blk % TPP;
    int c  = (blk / TPP) % CC;
    int b  = (blk / (TPP * CC)) % BB;
    int t  =  blk / (TPP * CC * BB);
    int f0 = t * CHUNK + tp * 2;
    const float* xb = x + ((size_t)(b * CC + c) * 232 + f0) * (HH * WW);
    size_t obase = ((size_t)((t * BB + b) * RR + (c * TPP + tp))) * D_INF;
    __half* oh = g_feat_h + obase;
    __half* ol = g_feat_l + obase;
    for (int d = threadIdx.x; d < HP * WP; d += blockDim.x) {
        int hp = d >> 5, wp = d & 31;
        const float* p = xb + (hp * 2) * WW + wp * 2;
        float s = 0.f;
#pragma unroll
        for (int kd = 0; kd < 3; kd++) {
            const float* pf = p + kd * (HH * WW);
            float2 a0 = *(const float2*)pf;
            float2 a1 = *(const float2*)(pf + WW);
            s += (a0.x + a0.y) + (a1.x + a1.y);
        }
        float v = s / 12.0f;
        __half hi = __float2half_rn(v);
        __half lo = __float2half_rn(v - __half2float(hi));
        oh[d] = hi; ol[d] = lo;
    }
}

// ------------------------------ HMMA GEMM -----------------------------------
// C[M,N] = A[M,K] @ B[K,N]; B given as [N,K] hi/lo fp16 scaled by 32.
// Warps: 4(m) x 2(n); warp tile (BMT/4) x (BNT/2).
// IT = BMT/64 m16-steps, JT = BNT/16 n8-steps; B processed in j-groups
// (4 when JT==4 as in R9; 2 when JT==8 to cap live regs).
// EPI: 0 = store float cur; 1 = LIF -> half spk; 2 = LIF -> float spk
template<bool SPLIT_A, int BMT, int BNT, int NSTG, int MB, int EPI>
__global__ void __launch_bounds__(256, MB) hgemm_kernel(
    int M, int N, int K,
    const __half* __restrict__ Ah, const __half* __restrict__ Al,
    const __half* __restrict__ Bh, const __half* __restrict__ Bl,
    const float* __restrict__ bias,
    float* __restrict__ Cout,
    float* __restrict__ mem, void* __restrict__ spk,
    const float* __restrict__ betas, int bidx,
    const float* __restrict__ thrs,  int tidx)
{
    extern __shared__ char smem[];
    const int A_TILE  = BMT * PITCH;
    const int B_TILE  = BNT * PITCH;
    const int AL_OFF  = A_TILE;
    const int BH_OFF  = SPLIT_A ? 2 * A_TILE : A_TILE;
    const int BL_OFF  = BH_OFF + B_TILE;
    const int STAGE   = BL_OFF + B_TILE;
    const int IT      = BMT / 64;
    const int JT      = BNT / 16;
    const int JG      = (JT == 4) ? 4 : 2;
    uint32_t sb = smem_u32(smem);

    int tid  = threadIdx.x;
    int wid  = tid >> 5, lane = tid & 31;
    const int bm = blockIdx.y * BMT;
    const int bn = blockIdx.x * BNT;
    const int NIT = K / BKT;

    auto load_chunk = [&](int chunk, int s) {
        uint32_t st = sb + (uint32_t)s * STAGE;
        int k0 = chunk * BKT;
        const int NQ = ((SPLIT_A ? 2 * BMT : BMT) + 2 * BNT) * 4 / 256;
#pragma unroll
        for (int q = 0; q < NQ; q++) {
            int g = tid + (q << 8);
            int r = g >> 2, gran = g & 3;
            if (r < BMT) {
                cp_async16(st + r * PITCH + gran * 16,
                           Ah + (size_t)(bm + r) * K + k0 + gran * 8);
            } else if (SPLIT_A && r < 2 * BMT) {
                int ra = r - BMT;
                cp_async16(st + AL_OFF + ra * PITCH + gran * 16,
                           Al + (size_t)(bm + ra) * K + k0 + gran * 8);
            } else {
                int rb = r - (SPLIT_A ? 2 * BMT : BMT);
                if (rb < BNT) {
                    cp_async16(st + BH_OFF + rb * PITCH + gran * 16,
                               Bh + (size_t)(bn + rb) * K + k0 + gran * 8);
                } else {
                    rb -= BNT;
                    cp_async16(st + BL_OFF + rb * PITCH + gran * 16,
                               Bl + (size_t)(bn + rb) * K + k0 + gran * 8);
                }
            }
        }
    };

    float acc[IT][JT][4];
#pragma unroll
    for (int i = 0; i < IT; i++)
#pragma unroll
        for (int j = 0; j < JT; j++)
#pragma unroll
            for (int q = 0; q < 4; q++) acc[i][j][q] = 0.f;

    int mw = wid & 3, nw = wid >> 2;
    uint32_t a_lane = (uint32_t)((mw * (BMT / 4) + (lane & 15)) * PITCH + ((lane >> 4) << 4));
    uint32_t b_lane = (uint32_t)((nw * (BNT / 2) + (lane & 7)) * PITCH + ((lane >> 3) << 4));

#pragma unroll
    for (int p = 0; p < NSTG - 1; p++) {
        load_chunk(p, p);
        asm volatile("cp.async.commit_group;");
    }

    for (int it = 0; it < NIT; it++) {
        int pf = it + NSTG - 1;
        if (pf < NIT) load_chunk(pf, pf % NSTG);
        asm volatile("cp.async.commit_group;");
        asm volatile("cp.async.wait_group %0;" :: "n"(NSTG - 1));
        __syncthreads();

        uint32_t st = sb + (uint32_t)(it % NSTG) * STAGE;

        uint32_t a[IT][2][4];
#pragma unroll
        for (int i = 0; i < IT; i++)
#pragma unroll
            for (int s = 0; s < 2; s++)
                ldmx4(a[i][s], st + a_lane + (uint32_t)(i * 16 * PITCH + s * 32));

        uint32_t al[SPLIT_A ? IT : 1][2][4];
        if (SPLIT_A) {
#pragma unroll
            for (int i = 0; i < IT; i++)
#pragma unroll
                for (int s = 0; s < 2; s++)
                    ldmx4(al[i][s], st + AL_OFF + a_lane + (uint32_t)(i * 16 * PITCH + s * 32));
        }

#pragma unroll
        for (int jg = 0; jg < JT; jg += JG) {
            uint32_t bh[JG][4], bl[JG][4];
#pragma unroll
            for (int jj = 0; jj < JG; jj++)
                ldmx4(bh[jj], st + BH_OFF + b_lane + (uint32_t)((jg + jj) * 8 * PITCH));
#pragma unroll
            for (int jj = 0; jj < JG; jj++)
                ldmx4(bl[jj], st + BL_OFF + b_lane + (uint32_t)((jg + jj) * 8 * PITCH));

#pragma unroll
            for (int i = 0; i < IT; i++)
#pragma unroll
                for (int jj = 0; jj < JG; jj++) {
                    float* c = acc[i][jg + jj];
                    mma16816(c, a[i][0], bh[jj][0], bh[jj][1]);
                    mma16816(c, a[i][1], bh[jj][2], bh[jj][3]);
                    mma16816(c, a[i][0], bl[jj][0], bl[jj][1]);
                    mma16816(c, a[i][1], bl[jj][2], bl[jj][3]);
                }
            if (SPLIT_A) {
#pragma unroll
                for (int i = 0; i < IT; i++)
#pragma unroll
                    for (int jj = 0; jj < JG; jj++) {
                        float* c = acc[i][jg + jj];
                        mma16816(c, al[i][0], bh[jj][0], bh[jj][1]);
                        mma16816(c, al[i][1], bh[jj][2], bh[jj][3]);
                    }
            }
        }
        __syncthreads();
    }

    // ------------------------------ epilogue --------------------------------
    int rg = lane >> 2;
    int cq = (lane & 3) * 2;
    float beta = 0.f, thr = 0.f;
    if (EPI != 0) { beta = clamp01(betas[bidx]); thr = thrs[tidx]; }

#pragma unroll
    for (int i = 0; i < IT; i++) {
#pragma unroll
        for (int j = 0; j < JT; j++) {
            int cn = bn + nw * (BNT / 2) + j * 8 + cq;
            float bs0 = bias[cn], bs1 = bias[cn + 1];
#pragma unroll
            for (int h = 0; h < 2; h++) {
                int rm = bm + mw * (BMT / 4) + i * 16 + rg + h * 8;
                float cur0 = acc[i][j][2 * h + 0] * INV_SW + bs0;
                float cur1 = acc[i][j][2 * h + 1] * INV_SW + bs1;
                size_t off = (size_t)rm * N + cn;
                if (EPI == 0) {
                    *(float2*)(Cout + off) = make_float2(cur0, cur1);
                } else {
                    float2 m2 = *(const float2*)(mem + off);
                    float mn0 = beta * m2.x + cur0 - (m2.x > thr ? thr : 0.f);
                    float mn1 = beta * m2.y + cur1 - (m2.y > thr ? thr : 0.f);
                    float sp0 = (mn0 - thr) > 0.f ? 1.f : 0.f;
                    float sp1 = (mn1 - thr) > 0.f ? 1.f : 0.f;
                    *(float2*)(mem + off) = make_float2(mn0, mn1);
                    if (EPI == 1) {
                        *(__half2*)((__half*)spk + off) = __floats2half2_rn(sp0, sp1);
                    } else {
                        *(float2*)((float*)spk + off) = make_float2(sp0, sp1);
                    }
                }
            }
        }
    }
}

// ------------------------- LIF on precomputed cur_in ------------------------
__global__ void lif_in_kernel(const float* __restrict__ betas,
                              const float* __restrict__ thrs, int t) {
    int i = blockIdx.x * blockDim.x + threadIdx.x;
    float beta = clamp01(betas[0]);
    float thr  = thrs[0];
    const float4* cur4 = (const float4*)(g_curin + (size_t)t * MS * H0F);
    float4* m4p = (float4*)g_m_in;
    float4 m = m4p[i];
    float4 c = cur4[i];
    float mn0 = beta * m.x + c.x - (m.x > thr ? thr : 0.f);
    float mn1 = beta * m.y + c.y - (m.y > thr ? thr : 0.f);
    float mn2 = beta * m.z + c.z - (m.z > thr ? thr : 0.f);
    float mn3 = beta * m.w + c.w - (m.w > thr ? thr : 0.f);
    float sp0 = (mn0 - thr) > 0.f ? 1.f : 0.f;
    float sp1 = (mn1 - thr) > 0.f ? 1.f : 0.f;
    float sp2 = (mn2 - thr) > 0.f ? 1.f : 0.f;
    float sp3 = (mn3 - thr) > 0.f ? 1.f : 0.f;
    m4p[i] = make_float4(mn0, mn1, mn2, mn3);
    __half2* hp = (__half2*)g_spkin_h + 2 * (size_t)i;
    hp[0] = __floats2half2_rn(sp0, sp1);
    hp[1] = __floats2half2_rn(sp2, sp3);
}

// --------------------------- readout + output LIF ---------------------------
__global__ void out_kernel(const float* __restrict__ Wout,
                           const float* __restrict__ bout,
                           const float* __restrict__ betas,
                           float* __restrict__ out, int t) {
    __shared__ float red[4][256];
    int b = blockIdx.x;
    int tid = threadIdx.x;
    const float* s = g_spk2 + (size_t)b * FOUT;
    const float4* W4 = (const float4*)Wout;
    float a0 = 0.f, a1 = 0.f, a2 = 0.f, a3 = 0.f;
    for (int k = tid; k < FOUT; k += 256) {
        float sv = s[k];
        float4 w = W4[k];
        a0 += sv * w.x; a1 += sv * w.y; a2 += sv * w.z; a3 += sv * w.w;
    }
    red[0][tid] = a0; red[1][tid] = a1; red[2][tid] = a2; red[3][tid] = a3;
    __syncthreads();
    for (int off = 128; off > 0; off >>= 1) {
        if (tid < off) {
#pragma unroll
            for (int q = 0; q < 4; q++) red[q][tid] += red[q][tid + off];
        }
        __syncthreads();
    }
    if (tid == 0) {
        float beta = clamp01(betas[3]);
#pragma unroll
        for (int n = 0; n < 4; n++) {
            float cur = red[n][0] + bout[n];
            float m = g_m_out[b * 4 + n];
            float mn = beta * m + cur - (m > 1.0f ? 1.0f : 0.f);
            g_m_out[b * 4 + n] = mn;
            out[t * BB * NCLS + b * NCLS + n] = (mn - 1.0f) > 0.f ? 1.f : 0.f;
        }
    }
}

// ------------------------------- launch -------------------------------------
extern "C" void kernel_launch(void* const* d_in, const int* in_sizes, int n_in,
                              void* d_out, int out_size) {
    const float* x     = (const float*)d_in[0];
    const float* W_in  = (const float*)d_in[1];
    const float* b_in  = (const float*)d_in[2];
    const float* W_h1  = (const float*)d_in[3];
    const float* b_h1  = (const float*)d_in[4];
    const float* W_h2  = (const float*)d_in[5];
    const float* b_h2  = (const float*)d_in[6];
    const float* W_out = (const float*)d_in[7];
    const float* b_out = (const float*)d_in[8];
    const float* betas = (const float*)d_in[9];
    const float* thrs  = (const float*)d_in[10];
    float* out = (float*)d_out;

    __half *p_feat_h, *p_feat_l, *p_spkin, *p_spk1;
    __half *p_Winh, *p_Winl, *p_Wh1h, *p_Wh1l, *p_Wh2h, *p_Wh2l;
    float *p_curin, *p_m_h1, *p_m_h2, *p_spk2;
    cudaGetSymbolAddress((void**)&p_feat_h, g_feat_h);
    cudaGetSymbolAddress((void**)&p_feat_l, g_feat_l);
    cudaGetSymbolAddress((void**)&p_curin,  g_curin);
    cudaGetSymbolAddress((void**)&p_spkin,  g_spkin_h);
    cudaGetSymbolAddress((void**)&p_spk1,   g_spk1_h);
    cudaGetSymbolAddress((void**)&p_m_h1,   g_m_h1);
    cudaGetSymbolAddress((void**)&p_spk2,   g_spk2);
    cudaGetSymbolAddress((void**)&p_m_h2,   g_m_h2);
    cudaGetSymbolAddress((void**)&p_Winh,   g_Win_h);
    cudaGetSymbolAddress((void**)&p_Winl,   g_Win_l);
    cudaGetSymbolAddress((void**)&p_Wh1h,   g_Wh1_h);
    cudaGetSymbolAddress((void**)&p_Wh1l,   g_Wh1_l);
    cudaGetSymbolAddress((void**)&p_Wh2h,   g_Wh2_h);
    cudaGetSymbolAddress((void**)&p_Wh2l,   g_Wh2_l);

    // stage sizes:
    //   GEMM1 split 128x64 : (2*10240 + 2*5120)  x3 = 92160  (R9 config)
    //   GEMM2 256x128      : (20480 + 2*10240)   x3 = 122880 (occ 1, 255 regs)
    //   GEMM3 128x64       : (10240 + 2*5120)    x3 = 61440  (R9 config)
    const int SMEM1 = 3 * (2 * 128 * PITCH + 2 * 64 * PITCH);
    const int SMEM2 = 3 * (256 * PITCH + 2 * 128 * PITCH);
    const int SMEM3 = 3 * (128 * PITCH + 2 * 64 * PITCH);
    cudaFuncSetAttribute((const void*)hgemm_kernel<true, 128, 64, 3, 1, 0>,
                         cudaFuncAttributeMaxDynamicSharedMemorySize, SMEM1);
    cudaFuncSetAttribute((const void*)hgemm_kernel<false, 256, 128, 3, 1, 1>,
                         cudaFuncAttributeMaxDynamicSharedMemorySize, SMEM2);
    cudaFuncSetAttribute((const void*)hgemm_kernel<false, 128, 64, 3, 2, 2>,
                         cudaFuncAttributeMaxDynamicSharedMemorySize, SMEM3);

    // order chosen so ncu -s 5 -c 1 lands on GEMM1 (launch #6)
    split_tr_kernel<<<dim3(H0F / 32, D_INF / 32), dim3(32, 8)>>>(W_in, p_Winh, p_Winl, D_INF, H0F);
    split_tr_kernel<<<dim3(H1F / 32, H0F / 32),  dim3(32, 8)>>>(W_h1, p_Wh1h, p_Wh1l, H0F, H1F);
    split_tr_kernel<<<dim3(H2F / 32, H1F / 32),  dim3(32, 8)>>>(W_h2, p_Wh2h, p_Wh2l, H1F, H2F);

    pool_kernel<<<T_STEPS * BB * CC * TPP, 256>>>(x);

    zero_kernel<<<512, 256>>>();

    // GEMM1: cur_in_all = feat @ W_in + b_in   [14336, 2048], split-A 3-pass
    hgemm_kernel<true, 128, 64, 3, 1, 0><<<dim3(H0F / 64, M_ALL / 128), 256, SMEM1>>>(
        M_ALL, H0F, D_INF, p_feat_h, p_feat_l, p_Winh, p_Winl,
        b_in, p_curin, nullptr, nullptr, nullptr, 0, nullptr, 0);

    const int n4_lif_in = (MS * H0F) / 4;

    for (int t = 0; t < T_STEPS; t++) {
        lif_in_kernel<<<n4_lif_in / 256, 256>>>(betas, thrs, t);

        // GEMM2: spk_in @ W_h1 -> LIF -> spk1 (half); 256x128 tile, 112 CTAs
        hgemm_kernel<false, 256, 128, 3, 1, 1><<<dim3(H1F / 128, MS / 256), 256, SMEM2>>>(
            MS, H1F, H0F, p_spkin, nullptr, p_Wh1h, p_Wh1l,
            b_h1, nullptr, p_m_h1, p_spk1, betas, 1, thrs, 1);

        // GEMM3: spk1 @ W_h2 -> LIF -> spk2 (float); R9 config
        hgemm_kernel<false, 128, 64, 3, 2, 2><<<dim3(H2F / 64, MS / 128), 256, SMEM3>>>(
            MS, H2F, H1F, p_spk1, nullptr, p_Wh2h, p_Wh2l,
            b_h2, nullptr, p_m_h2, p_spk2, betas, 2, thrs, 2);

        out_kernel<<<BB, 256>>>(W_out, b_out, betas, out, t);
    }
}

// round 13
// speedup vs baseline: 1.2658x; 1.2658x over previous
#include <cuda_runtime.h>
#include <cuda_fp16.h>
#include <stdint.h>

// ---------------------------------------------------------------------------
// SNN: pool -> fc_in -> 3x LIF layers -> readout, T=8.
// Split-precision fp16 HMMA (mma.sync.m16n8k16), exact for spikes.
// R13: time-batched GEMMs. LIF recurrence factored into elementwise scan
// kernels (membrane in registers across t); all three GEMMs run once at
// M=14336 (full waves). Bit-identical numerics to R9.
// ---------------------------------------------------------------------------

#define T_STEPS 8
#define BB      32
#define CC      4
#define CHUNK   29
#define HH      64
#define WW      64
#define TPP     14
#define HP      32
#define WP      32
#define RR      56
#define D_INF   1024
#define H0F     2048
#define H1F     2048
#define H2F     1024
#define NCLS    4
#define MS      (BB*RR)         // 1792
#define M_ALL   (T_STEPS*MS)    // 14336
#define FOUT    (RR*H2F)        // 57344

#define SCALE_W 32.0f
#define INV_SW  (1.0f/32.0f)

#define BKT   32
#define PITCH 80

// ------------------------- static scratch ----------------------------------
__device__ __half g_feat_h[(size_t)M_ALL * D_INF];
__device__ __half g_feat_l[(size_t)M_ALL * D_INF];
__device__ float  g_cur   [(size_t)M_ALL * H0F];    // cur_in, then cur1, then cur2
__device__ __half g_spkin_h[(size_t)M_ALL * H0F];
__device__ __half g_spk1_h [(size_t)M_ALL * H1F];
__device__ float  g_spk2   [(size_t)M_ALL * H2F];
__device__ __half g_Win_h[(size_t)H0F * D_INF];
__device__ __half g_Win_l[(size_t)H0F * D_INF];
__device__ __half g_Wh1_h[(size_t)H1F * H0F];
__device__ __half g_Wh1_l[(size_t)H1F * H0F];
__device__ __half g_Wh2_h[(size_t)H2F * H1F];
__device__ __half g_Wh2_l[(size_t)H2F * H1F];

__device__ __forceinline__ float clamp01(float v) {
    return fminf(fmaxf(v, 0.0f), 1.0f);
}
__device__ __forceinline__ uint32_t smem_u32(const void* p) {
    uint32_t a;
    asm("{ .reg .u64 t; cvta.to.shared.u64 t, %1; cvt.u32.u64 %0, t; }" : "=r"(a) : "l"(p));
    return a;
}
__device__ __forceinline__ void cp_async16(uint32_t dst, const void* src) {
    asm volatile("cp.async.cg.shared.global [%0], [%1], 16;" :: "r"(dst), "l"(src));
}
__device__ __forceinline__ void ldmx4(uint32_t* r, uint32_t addr) {
    asm volatile("ldmatrix.sync.aligned.m8n8.x4.shared.b16 {%0,%1,%2,%3}, [%4];"
        : "=r"(r[0]), "=r"(r[1]), "=r"(r[2]), "=r"(r[3]) : "r"(addr));
}
__device__ __forceinline__ void mma16816(float* c, const uint32_t* a,
                                         uint32_t b0, uint32_t b1) {
    asm volatile(
        "mma.sync.aligned.m16n8k16.row.col.f32.f16.f16.f32 "
        "{%0,%1,%2,%3}, {%4,%5,%6,%7}, {%8,%9}, {%0,%1,%2,%3};"
        : "+f"(c[0]), "+f"(c[1]), "+f"(c[2]), "+f"(c[3])
        : "r"(a[0]), "r"(a[1]), "r"(a[2]), "r"(a[3]), "r"(b0), "r"(b1));
}

// ------------------------- weight split + transpose -------------------------
__global__ void split_tr_kernel(const float* __restrict__ W,
                                __half* __restrict__ Th, __half* __restrict__ Tl,
                                int K, int N) {
    __shared__ float tile[32][33];
    int n0 = blockIdx.x * 32, k0 = blockIdx.y * 32;
    int tx = threadIdx.x, ty = threadIdx.y;   // 32 x 8
#pragma unroll
    for (int j = 0; j < 32; j += 8)
        tile[ty + j][tx] = W[(size_t)(k0 + ty + j) * N + n0 + tx];
    __syncthreads();
#pragma unroll
    for (int j = 0; j < 32; j += 8) {
        float w = tile[tx][ty + j] * SCALE_W;
        __half hi = __float2half_rn(w);
        __half lo = __float2half_rn(w - __half2float(hi));
        size_t o = (size_t)(n0 + ty + j) * K + k0 + tx;
        Th[o] = hi; Tl[o] = lo;
    }
}

// ------------------------------- avg pool 3d --------------------------------
__global__ void pool_kernel(const float* __restrict__ x) {
    int blk = blockIdx.x;
    int tp = blk % TPP;
    int c  = (blk / TPP) % CC;
    int b  = (blk / (TPP * CC)) % BB;
    int t  =  blk / (TPP * CC * BB);
    int f0 = t * CHUNK + tp * 2;
    const float* xb = x + ((size_t)(b * CC + c) * 232 + f0) * (HH * WW);
    size_t obase = ((size_t)((t * BB + b) * RR + (c * TPP + tp))) * D_INF;
    __half* oh = g_feat_h + obase;
    __half* ol = g_feat_l + obase;
    for (int d = threadIdx.x; d < HP * WP; d += blockDim.x) {
        int hp = d >> 5, wp = d & 31;
        const float* p = xb + (hp * 2) * WW + wp * 2;
        float s = 0.f;
#pragma unroll
        for (int kd = 0; kd < 3; kd++) {
            const float* pf = p + kd * (HH * WW);
            float2 a0 = *(const float2*)pf;
            float2 a1 = *(const float2*)(pf + WW);
            s += (a0.x + a0.y) + (a1.x + a1.y);
        }
        float v = s / 12.0f;
        __half hi = __float2half_rn(v);
        __half lo = __float2half_rn(v - __half2float(hi));
        oh[d] = hi; ol[d] = lo;
    }
}

// ------------------------------ HMMA GEMM -----------------------------------
// C[M,N] = A[M,K] @ B[K,N] + bias; B given as [N,K] hi/lo fp16 scaled by 32.
// 128x64 CTA tile, warps 4(m) x 2(n), warp tile 32x32, 3-stage cp.async.
template<bool SPLIT_A>
__global__ void __launch_bounds__(256, SPLIT_A ? 1 : 2) hgemm_kernel(
    int M, int N, int K,
    const __half* __restrict__ Ah, const __half* __restrict__ Al,
    const __half* __restrict__ Bh, const __half* __restrict__ Bl,
    const float* __restrict__ bias,
    float* __restrict__ Cout)
{
    extern __shared__ char smem[];
    const int BMT = 128, BNT = 64, NSTG = 3;
    const int A_TILE = BMT * PITCH;
    const int B_TILE = BNT * PITCH;
    const int AL_OFF = A_TILE;
    const int BH_OFF = SPLIT_A ? 2 * A_TILE : A_TILE;
    const int BL_OFF = BH_OFF + B_TILE;
    const int STAGE  = BL_OFF + B_TILE;
    uint32_t sb = smem_u32(smem);

    int tid  = threadIdx.x;
    int wid  = tid >> 5, lane = tid & 31;
    const int bm = blockIdx.y * BMT;
    const int bn = blockIdx.x * BNT;
    const int NIT = K / BKT;

    auto load_chunk = [&](int chunk, int s) {
        uint32_t st = sb + (uint32_t)s * STAGE;
        int k0 = chunk * BKT;
        const int NQ = ((SPLIT_A ? 2 * BMT : BMT) + 2 * BNT) * 4 / 256;
#pragma unroll
        for (int q = 0; q < NQ; q++) {
            int g = tid + (q << 8);
            int r = g >> 2, gran = g & 3;
            if (r < BMT) {
                cp_async16(st + r * PITCH + gran * 16,
                           Ah + (size_t)(bm + r) * K + k0 + gran * 8);
            } else if (SPLIT_A && r < 2 * BMT) {
                int ra = r - BMT;
                cp_async16(st + AL_OFF + ra * PITCH + gran * 16,
                           Al + (size_t)(bm + ra) * K + k0 + gran * 8);
            } else {
                int rb = r - (SPLIT_A ? 2 * BMT : BMT);
                if (rb < BNT) {
                    cp_async16(st + BH_OFF + rb * PITCH + gran * 16,
                               Bh + (size_t)(bn + rb) * K + k0 + gran * 8);
                } else {
                    rb -= BNT;
                    cp_async16(st + BL_OFF + rb * PITCH + gran * 16,
                               Bl + (size_t)(bn + rb) * K + k0 + gran * 8);
                }
            }
        }
    };

    float acc[2][4][4];
#pragma unroll
    for (int i = 0; i < 2; i++)
#pragma unroll
        for (int j = 0; j < 4; j++)
#pragma unroll
            for (int q = 0; q < 4; q++) acc[i][j][q] = 0.f;

    int mw = wid & 3, nw = wid >> 2;
    uint32_t a_lane = (uint32_t)((mw * 32 + (lane & 15)) * PITCH + ((lane >> 4) << 4));
    uint32_t b_lane = (uint32_t)((nw * 32 + (lane & 7)) * PITCH + ((lane >> 3) << 4));

#pragma unroll
    for (int p = 0; p < NSTG - 1; p++) {
        load_chunk(p, p);
        asm volatile("cp.async.commit_group;");
    }

    for (int it = 0; it < NIT; it++) {
        int pf = it + NSTG - 1;
        if (pf < NIT) load_chunk(pf, pf % NSTG);
        asm volatile("cp.async.commit_group;");
        asm volatile("cp.async.wait_group %0;" :: "n"(NSTG - 1));
        __syncthreads();

        uint32_t st = sb + (uint32_t)(it % NSTG) * STAGE;

        uint32_t a[2][2][4];
#pragma unroll
        for (int i = 0; i < 2; i++)
#pragma unroll
            for (int s = 0; s < 2; s++)
                ldmx4(a[i][s], st + a_lane + (uint32_t)(i * 16 * PITCH + s * 32));

        uint32_t al[SPLIT_A ? 2 : 1][2][4];
        if (SPLIT_A) {
#pragma unroll
            for (int i = 0; i < 2; i++)
#pragma unroll
                for (int s = 0; s < 2; s++)
                    ldmx4(al[i][s], st + AL_OFF + a_lane + (uint32_t)(i * 16 * PITCH + s * 32));
        }

        uint32_t bh[4][4], bl[4][4];
#pragma unroll
        for (int j = 0; j < 4; j++)
            ldmx4(bh[j], st + BH_OFF + b_lane + (uint32_t)(j * 8 * PITCH));
#pragma unroll
        for (int j = 0; j < 4; j++)
            ldmx4(bl[j], st + BL_OFF + b_lane + (uint32_t)(j * 8 * PITCH));

#pragma unroll
        for (int i = 0; i < 2; i++)
#pragma unroll
            for (int j = 0; j < 4; j++) {
                float* c = acc[i][j];
                mma16816(c, a[i][0], bh[j][0], bh[j][1]);
                mma16816(c, a[i][1], bh[j][2], bh[j][3]);
                mma16816(c, a[i][0], bl[j][0], bl[j][1]);
                mma16816(c, a[i][1], bl[j][2], bl[j][3]);
            }
        if (SPLIT_A) {
#pragma unroll
            for (int i = 0; i < 2; i++)
#pragma unroll
                for (int j = 0; j < 4; j++) {
                    float* c = acc[i][j];
                    mma16816(c, al[i][0], bh[j][0], bh[j][1]);
                    mma16816(c, al[i][1], bh[j][2], bh[j][3]);
                }
        }
        __syncthreads();
    }

    // epilogue: cur = acc/32 + bias
    int rg = lane >> 2;
    int cq = (lane & 3) * 2;
#pragma unroll
    for (int i = 0; i < 2; i++) {
#pragma unroll
        for (int j = 0; j < 4; j++) {
            int cn = bn + nw * 32 + j * 8 + cq;
            float bs0 = bias[cn], bs1 = bias[cn + 1];
#pragma unroll
            for (int h = 0; h < 2; h++) {
                int rm = bm + mw * 32 + i * 16 + rg + h * 8;
                float cur0 = acc[i][j][2 * h + 0] * INV_SW + bs0;
                float cur1 = acc[i][j][2 * h + 1] * INV_SW + bs1;
                *(float2*)(Cout + (size_t)rm * N + cn) = make_float2(cur0, cur1);
            }
        }
    }
}

// ------------------------- LIF scan over timesteps --------------------------
// cur layout [T, MS, NF] fp32; membrane in registers across t.
// OUTF 0: write half spikes; OUTF 1: write float spikes.
template<int OUTF>
__global__ void lif_scan_kernel(const float* __restrict__ cur,
                                void* __restrict__ spk, int NF,
                                const float* __restrict__ betas, int bidx,
                                const float* __restrict__ thrs,  int tidx) {
    size_t e = ((size_t)blockIdx.x * blockDim.x + threadIdx.x) * 4;
    float beta = clamp01(betas[bidx]);
    float thr  = thrs[tidx];
    float m0 = 0.f, m1 = 0.f, m2 = 0.f, m3 = 0.f;
    size_t step = (size_t)MS * NF;
#pragma unroll
    for (int t = 0; t < T_STEPS; t++) {
        float4 c = *(const float4*)(cur + t * step + e);
        float mn0 = beta * m0 + c.x - (m0 > thr ? thr : 0.f);
        float mn1 = beta * m1 + c.y - (m1 > thr ? thr : 0.f);
        float mn2 = beta * m2 + c.z - (m2 > thr ? thr : 0.f);
        float mn3 = beta * m3 + c.w - (m3 > thr ? thr : 0.f);
        float sp0 = (mn0 - thr) > 0.f ? 1.f : 0.f;
        float sp1 = (mn1 - thr) > 0.f ? 1.f : 0.f;
        float sp2 = (mn2 - thr) > 0.f ? 1.f : 0.f;
        float sp3 = (mn3 - thr) > 0.f ? 1.f : 0.f;
        if (OUTF == 0) {
            __half2* hp = (__half2*)((__half*)spk + t * step + e);
            hp[0] = __floats2half2_rn(sp0, sp1);
            hp[1] = __floats2half2_rn(sp2, sp3);
        } else {
            *(float4*)((float*)spk + t * step + e) = make_float4(sp0, sp1, sp2, sp3);
        }
        m0 = mn0; m1 = mn1; m2 = mn2; m3 = mn3;
    }
}

// --------------------------- readout + output LIF ---------------------------
// One block per batch element; loops t internally; membrane in tid-0 regs.
__global__ void out_kernel(const float* __restrict__ Wout,
                           const float* __restrict__ bout,
                           const float* __restrict__ betas,
                           float* __restrict__ out) {
    __shared__ float red[4][256];
    int b = blockIdx.x;
    int tid = threadIdx.x;
    const float4* W4 = (const float4*)Wout;
    float beta = clamp01(betas[3]);
    float m[4] = {0.f, 0.f, 0.f, 0.f};
    for (int t = 0; t < T_STEPS; t++) {
        const float* s = g_spk2 + ((size_t)t * MS + b * RR) * H2F;
        float a0 = 0.f, a1 = 0.f, a2 = 0.f, a3 = 0.f;
        for (int k = tid; k < FOUT; k += 256) {
            float sv = s[k];
            float4 w = W4[k];
            a0 += sv * w.x; a1 += sv * w.y; a2 += sv * w.z; a3 += sv * w.w;
        }
        red[0][tid] = a0; red[1][tid] = a1; red[2][tid] = a2; red[3][tid] = a3;
        __syncthreads();
        for (int off = 128; off > 0; off >>= 1) {
            if (tid < off) {
#pragma unroll
                for (int q = 0; q < 4; q++) red[q][tid] += red[q][tid + off];
            }
            __syncthreads();
        }
        if (tid == 0) {
#pragma unroll
            for (int n = 0; n < 4; n++) {
                float cur = red[n][0] + bout[n];
                float mn = beta * m[n] + cur - (m[n] > 1.0f ? 1.0f : 0.f);
                m[n] = mn;
                out[t * BB * NCLS + b * NCLS + n] = (mn - 1.0f) > 0.f ? 1.f : 0.f;
            }
        }
        __syncthreads();
    }
}

// ------------------------------- launch -------------------------------------
extern "C" void kernel_launch(void* const* d_in, const int* in_sizes, int n_in,
                              void* d_out, int out_size) {
    const float* x     = (const float*)d_in[0];
    const float* W_in  = (const float*)d_in[1];
    const float* b_in  = (const float*)d_in[2];
    const float* W_h1  = (const float*)d_in[3];
    const float* b_h1  = (const float*)d_in[4];
    const float* W_h2  = (const float*)d_in[5];
    const float* b_h2  = (const float*)d_in[6];
    const float* W_out = (const float*)d_in[7];
    const float* b_out = (const float*)d_in[8];
    const float* betas = (const float*)d_in[9];
    const float* thrs  = (const float*)d_in[10];
    float* out = (float*)d_out;

    __half *p_feat_h, *p_feat_l, *p_spkin, *p_spk1;
    __half *p_Winh, *p_Winl, *p_Wh1h, *p_Wh1l, *p_Wh2h, *p_Wh2l;
    float *p_cur, *p_spk2;
    cudaGetSymbolAddress((void**)&p_feat_h, g_feat_h);
    cudaGetSymbolAddress((void**)&p_feat_l, g_feat_l);
    cudaGetSymbolAddress((void**)&p_cur,    g_cur);
    cudaGetSymbolAddress((void**)&p_spkin,  g_spkin_h);
    cudaGetSymbolAddress((void**)&p_spk1,   g_spk1_h);
    cudaGetSymbolAddress((void**)&p_spk2,   g_spk2);
    cudaGetSymbolAddress((void**)&p_Winh,   g_Win_h);
    cudaGetSymbolAddress((void**)&p_Winl,   g_Win_l);
    cudaGetSymbolAddress((void**)&p_Wh1h,   g_Wh1_h);
    cudaGetSymbolAddress((void**)&p_Wh1l,   g_Wh1_l);
    cudaGetSymbolAddress((void**)&p_Wh2h,   g_Wh2_h);
    cudaGetSymbolAddress((void**)&p_Wh2l,   g_Wh2_l);

    const int SMEM1 = 3 * (2 * 128 * PITCH + 2 * 64 * PITCH);   // 92160
    const int SMEM2 = 3 * (128 * PITCH + 2 * 64 * PITCH);       // 61440
    cudaFuncSetAttribute((const void*)hgemm_kernel<true>,
                         cudaFuncAttributeMaxDynamicSharedMemorySize, SMEM1);
    cudaFuncSetAttribute((const void*)hgemm_kernel<false>,
                         cudaFuncAttributeMaxDynamicSharedMemorySize, SMEM2);

    // launch order: gemm1 sits at launch idx 3 (where ncu -s captures)
    pool_kernel<<<T_STEPS * BB * CC * TPP, 256>>>(x);                       // 0
    split_tr_kernel<<<dim3(H0F / 32, D_INF / 32), dim3(32, 8)>>>(
        W_in, p_Winh, p_Winl, D_INF, H0F);                                   // 1
    split_tr_kernel<<<dim3(H1F / 32, H0F / 32),  dim3(32, 8)>>>(
        W_h1, p_Wh1h, p_Wh1l, H0F, H1F);                                     // 2

    // GEMM1: cur_in = feat @ W_in + b_in   [14336, 2048]
    hgemm_kernel<true><<<dim3(H0F / 64, M_ALL / 128), 256, SMEM1>>>(         // 3
        M_ALL, H0F, D_INF, p_feat_h, p_feat_l, p_Winh, p_Winl, b_in, p_cur);

    // input-layer LIF scan: cur_in -> spk_in (half), all t
    lif_scan_kernel<0><<<(MS * H0F / 4) / 256, 256>>>(                        // 4
        p_cur, p_spkin, H0F, betas, 0, thrs, 0);

    split_tr_kernel<<<dim3(H2F / 32, H1F / 32),  dim3(32, 8)>>>(
        W_h2, p_Wh2h, p_Wh2l, H1F, H2F);                                     // 5

    // GEMM2 (time-batched): cur1 = spk_in @ W_h1 + b_h1   [14336, 2048]
    hgemm_kernel<false><<<dim3(H1F / 64, M_ALL / 128), 256, SMEM2>>>(        // 6
        M_ALL, H1F, H0F, p_spkin, nullptr, p_Wh1h, p_Wh1l, b_h1, p_cur);

    // layer-1 LIF scan: cur1 -> spk1 (half)
    lif_scan_kernel<0><<<(MS * H1F / 4) / 256, 256>>>(                        // 7
        p_cur, p_spk1, H1F, betas, 1, thrs, 1);

    // GEMM3 (time-batched): cur2 = spk1 @ W_h2 + b_h2   [14336, 1024]
    hgemm_kernel<false><<<dim3(H2F / 64, M_ALL / 128), 256, SMEM2>>>(        // 8
        M_ALL, H2F, H1F, p_spk1, nullptr, p_Wh2h, p_Wh2l, b_h2, p_cur);

    // layer-2 LIF scan: cur2 -> spk2 (float)
    lif_scan_kernel<1><<<(MS * H2F / 4) / 256, 256>>>(                        // 9
        p_cur, p_spk2, H2F, betas, 2, thrs, 2);

    // readout + output LIF (loops t internally)
    out_kernel<<<BB, 256>>>(W_out, b_out, betas, out);                        // 10
}

// round 14
// speedup vs baseline: 1.5884x; 1.2549x over previous
#include <cuda_runtime.h>
#include <cuda_fp16.h>
#include <stdint.h>

// ---------------------------------------------------------------------------
// SNN: pool -> fc_in -> 3x LIF layers -> readout, T=8.
// Split-precision fp16 HMMA, exact for spikes. Time-batched GEMMs.
// R14: GEMM2/3 use 64x64 warp tiles (128x256 CTA, occ 1, ~196 regs) halving
// ldsm bytes/MAC; readout split into parallel matvec + tiny LIF scan.
// ---------------------------------------------------------------------------

#define T_STEPS 8
#define BB      32
#define CC      4
#define CHUNK   29
#define HH      64
#define WW      64
#define TPP     14
#define HP      32
#define WP      32
#define RR      56
#define D_INF   1024
#define H0F     2048
#define H1F     2048
#define H2F     1024
#define NCLS    4
#define MS      (BB*RR)         // 1792
#define M_ALL   (T_STEPS*MS)    // 14336
#define FOUT    (RR*H2F)        // 57344

#define SCALE_W 32.0f
#define INV_SW  (1.0f/32.0f)

#define BKT   32
#define PITCH 80

// ------------------------- static scratch ----------------------------------
__device__ __half g_feat_h[(size_t)M_ALL * D_INF];
__device__ __half g_feat_l[(size_t)M_ALL * D_INF];
__device__ float  g_cur   [(size_t)M_ALL * H0F];
__device__ __half g_spkin_h[(size_t)M_ALL * H0F];
__device__ __half g_spk1_h [(size_t)M_ALL * H1F];
__device__ float  g_spk2   [(size_t)M_ALL * H2F];
__device__ float  g_curout [T_STEPS * BB * NCLS];
__device__ __half g_Win_h[(size_t)H0F * D_INF];
__device__ __half g_Win_l[(size_t)H0F * D_INF];
__device__ __half g_Wh1_h[(size_t)H1F * H0F];
__device__ __half g_Wh1_l[(size_t)H1F * H0F];
__device__ __half g_Wh2_h[(size_t)H2F * H1F];
__device__ __half g_Wh2_l[(size_t)H2F * H1F];

__device__ __forceinline__ float clamp01(float v) {
    return fminf(fmaxf(v, 0.0f), 1.0f);
}
__device__ __forceinline__ uint32_t smem_u32(const void* p) {
    uint32_t a;
    asm("{ .reg .u64 t; cvta.to.shared.u64 t, %1; cvt.u32.u64 %0, t; }" : "=r"(a) : "l"(p));
    return a;
}
__device__ __forceinline__ void cp_async16(uint32_t dst, const void* src) {
    asm volatile("cp.async.cg.shared.global [%0], [%1], 16;" :: "r"(dst), "l"(src));
}
__device__ __forceinline__ void ldmx4(uint32_t* r, uint32_t addr) {
    asm volatile("ldmatrix.sync.aligned.m8n8.x4.shared.b16 {%0,%1,%2,%3}, [%4];"
        : "=r"(r[0]), "=r"(r[1]), "=r"(r[2]), "=r"(r[3]) : "r"(addr));
}
__device__ __forceinline__ void mma16816(float* c, const uint32_t* a,
                                         uint32_t b0, uint32_t b1) {
    asm volatile(
        "mma.sync.aligned.m16n8k16.row.col.f32.f16.f16.f32 "
        "{%0,%1,%2,%3}, {%4,%5,%6,%7}, {%8,%9}, {%0,%1,%2,%3};"
        : "+f"(c[0]), "+f"(c[1]), "+f"(c[2]), "+f"(c[3])
        : "r"(a[0]), "r"(a[1]), "r"(a[2]), "r"(a[3]), "r"(b0), "r"(b1));
}

// ------------------------- weight split + transpose -------------------------
__global__ void split_tr_kernel(const float* __restrict__ W,
                                __half* __restrict__ Th, __half* __restrict__ Tl,
                                int K, int N) {
    __shared__ float tile[32][33];
    int n0 = blockIdx.x * 32, k0 = blockIdx.y * 32;
    int tx = threadIdx.x, ty = threadIdx.y;   // 32 x 8
#pragma unroll
    for (int j = 0; j < 32; j += 8)
        tile[ty + j][tx] = W[(size_t)(k0 + ty + j) * N + n0 + tx];
    __syncthreads();
#pragma unroll
    for (int j = 0; j < 32; j += 8) {
        float w = tile[tx][ty + j] * SCALE_W;
        __half hi = __float2half_rn(w);
        __half lo = __float2half_rn(w - __half2float(hi));
        size_t o = (size_t)(n0 + ty + j) * K + k0 + tx;
        Th[o] = hi; Tl[o] = lo;
    }
}

// ------------------------------- avg pool 3d --------------------------------
__global__ void pool_kernel(const float* __restrict__ x) {
    int blk = blockIdx.x;
    int tp = blk % TPP;
    int c  = (blk / TPP) % CC;
    int b  = (blk / (TPP * CC)) % BB;
    int t  =  blk / (TPP * CC * BB);
    int f0 = t * CHUNK + tp * 2;
    const float* xb = x + ((size_t)(b * CC + c) * 232 + f0) * (HH * WW);
    size_t obase = ((size_t)((t * BB + b) * RR + (c * TPP + tp))) * D_INF;
    __half* oh = g_feat_h + obase;
    __half* ol = g_feat_l + obase;
    for (int d = threadIdx.x; d < HP * WP; d += blockDim.x) {
        int hp = d >> 5, wp = d & 31;
        const float* p = xb + (hp * 2) * WW + wp * 2;
        float s = 0.f;
#pragma unroll
        for (int kd = 0; kd < 3; kd++) {
            const float* pf = p + kd * (HH * WW);
            float2 a0 = *(const float2*)pf;
            float2 a1 = *(const float2*)(pf + WW);
            s += (a0.x + a0.y) + (a1.x + a1.y);
        }
        float v = s / 12.0f;
        __half hi = __float2half_rn(v);
        __half lo = __float2half_rn(v - __half2float(hi));
        oh[d] = hi; ol[d] = lo;
    }
}

// ------------------- HMMA GEMM, 32x32 warp tile (GEMM1) ---------------------
template<bool SPLIT_A>
__global__ void __launch_bounds__(256, SPLIT_A ? 1 : 2) hgemm_kernel(
    int M, int N, int K,
    const __half* __restrict__ Ah, const __half* __restrict__ Al,
    const __half* __restrict__ Bh, const __half* __restrict__ Bl,
    const float* __restrict__ bias,
    float* __restrict__ Cout)
{
    extern __shared__ char smem[];
    const int BMT = 128, BNT = 64, NSTG = 3;
    const int A_TILE = BMT * PITCH;
    const int B_TILE = BNT * PITCH;
    const int AL_OFF = A_TILE;
    const int BH_OFF = SPLIT_A ? 2 * A_TILE : A_TILE;
    const int BL_OFF = BH_OFF + B_TILE;
    const int STAGE  = BL_OFF + B_TILE;
    uint32_t sb = smem_u32(smem);

    int tid  = threadIdx.x;
    int wid  = tid >> 5, lane = tid & 31;
    const int bm = blockIdx.y * BMT;
    const int bn = blockIdx.x * BNT;
    const int NIT = K / BKT;

    auto load_chunk = [&](int chunk, int s) {
        uint32_t st = sb + (uint32_t)s * STAGE;
        int k0 = chunk * BKT;
        const int NQ = ((SPLIT_A ? 2 * BMT : BMT) + 2 * BNT) * 4 / 256;
#pragma unroll
        for (int q = 0; q < NQ; q++) {
            int g = tid + (q << 8);
            int r = g >> 2, gran = g & 3;
            if (r < BMT) {
                cp_async16(st + r * PITCH + gran * 16,
                           Ah + (size_t)(bm + r) * K + k0 + gran * 8);
            } else if (SPLIT_A && r < 2 * BMT) {
                int ra = r - BMT;
                cp_async16(st + AL_OFF + ra * PITCH + gran * 16,
                           Al + (size_t)(bm + ra) * K + k0 + gran * 8);
            } else {
                int rb = r - (SPLIT_A ? 2 * BMT : BMT);
                if (rb < BNT) {
                    cp_async16(st + BH_OFF + rb * PITCH + gran * 16,
                               Bh + (size_t)(bn + rb) * K + k0 + gran * 8);
                } else {
                    rb -= BNT;
                    cp_async16(st + BL_OFF + rb * PITCH + gran * 16,
                               Bl + (size_t)(bn + rb) * K + k0 + gran * 8);
                }
            }
        }
    };

    float acc[2][4][4];
#pragma unroll
    for (int i = 0; i < 2; i++)
#pragma unroll
        for (int j = 0; j < 4; j++)
#pragma unroll
            for (int q = 0; q < 4; q++) acc[i][j][q] = 0.f;

    int mw = wid & 3, nw = wid >> 2;
    uint32_t a_lane = (uint32_t)((mw * 32 + (lane & 15)) * PITCH + ((lane >> 4) << 4));
    uint32_t b_lane = (uint32_t)((nw * 32 + (lane & 7)) * PITCH + ((lane >> 3) << 4));

#pragma unroll
    for (int p = 0; p < NSTG - 1; p++) {
        load_chunk(p, p);
        asm volatile("cp.async.commit_group;");
    }

    for (int it = 0; it < NIT; it++) {
        int pf = it + NSTG - 1;
        if (pf < NIT) load_chunk(pf, pf % NSTG);
        asm volatile("cp.async.commit_group;");
        asm volatile("cp.async.wait_group %0;" :: "n"(NSTG - 1));
        __syncthreads();

        uint32_t st = sb + (uint32_t)(it % NSTG) * STAGE;

        uint32_t a[2][2][4];
#pragma unroll
        for (int i = 0; i < 2; i++)
#pragma unroll
            for (int s = 0; s < 2; s++)
                ldmx4(a[i][s], st + a_lane + (uint32_t)(i * 16 * PITCH + s * 32));

        uint32_t al[SPLIT_A ? 2 : 1][2][4];
        if (SPLIT_A) {
#pragma unroll
            for (int i = 0; i < 2; i++)
#pragma unroll
                for (int s = 0; s < 2; s++)
                    ldmx4(al[i][s], st + AL_OFF + a_lane + (uint32_t)(i * 16 * PITCH + s * 32));
        }

        uint32_t bh[4][4], bl[4][4];
#pragma unroll
        for (int j = 0; j < 4; j++)
            ldmx4(bh[j], st + BH_OFF + b_lane + (uint32_t)(j * 8 * PITCH));
#pragma unroll
        for (int j = 0; j < 4; j++)
            ldmx4(bl[j], st + BL_OFF + b_lane + (uint32_t)(j * 8 * PITCH));

#pragma unroll
        for (int i = 0; i < 2; i++)
#pragma unroll
            for (int j = 0; j < 4; j++) {
                float* c = acc[i][j];
                mma16816(c, a[i][0], bh[j][0], bh[j][1]);
                mma16816(c, a[i][1], bh[j][2], bh[j][3]);
                mma16816(c, a[i][0], bl[j][0], bl[j][1]);
                mma16816(c, a[i][1], bl[j][2], bl[j][3]);
            }
        if (SPLIT_A) {
#pragma unroll
            for (int i = 0; i < 2; i++)
#pragma unroll
                for (int j = 0; j < 4; j++) {
                    float* c = acc[i][j];
                    mma16816(c, al[i][0], bh[j][0], bh[j][1]);
                    mma16816(c, al[i][1], bh[j][2], bh[j][3]);
                }
        }
        __syncthreads();
    }

    int rg = lane >> 2;
    int cq = (lane & 3) * 2;
#pragma unroll
    for (int i = 0; i < 2; i++) {
#pragma unroll
        for (int j = 0; j < 4; j++) {
            int cn = bn + nw * 32 + j * 8 + cq;
            float bs0 = bias[cn], bs1 = bias[cn + 1];
#pragma unroll
            for (int h = 0; h < 2; h++) {
                int rm = bm + mw * 32 + i * 16 + rg + h * 8;
                float cur0 = acc[i][j][2 * h + 0] * INV_SW + bs0;
                float cur1 = acc[i][j][2 * h + 1] * INV_SW + bs1;
                *(float2*)(Cout + (size_t)rm * N + cn) = make_float2(cur0, cur1);
            }
        }
    }
}

// ------------------- HMMA GEMM, 64x64 warp tile (GEMM2/3) -------------------
// CTA 128(m) x 256(n); warps 2(m) x 4(n); warp tile 64x64; NSTG=3; occ 1.
__global__ void __launch_bounds__(256, 1) hgemm_wide_kernel(
    int M, int N, int K,
    const __half* __restrict__ Ah,
    const __half* __restrict__ Bh, const __half* __restrict__ Bl,
    const float* __restrict__ bias,
    float* __restrict__ Cout)
{
    extern __shared__ char smem[];
    const int BMT = 128, BNT = 256, NSTG = 3;
    const int A_TILE = BMT * PITCH;     // 10240
    const int B_TILE = BNT * PITCH;     // 20480
    const int BH_OFF = A_TILE;
    const int BL_OFF = BH_OFF + B_TILE;
    const int STAGE  = BL_OFF + B_TILE; // 51200
    uint32_t sb = smem_u32(smem);

    int tid  = threadIdx.x;
    int wid  = tid >> 5, lane = tid & 31;
    const int bm = blockIdx.y * BMT;
    const int bn = blockIdx.x * BNT;
    const int NIT = K / BKT;

    auto load_chunk = [&](int chunk, int s) {
        uint32_t st = sb + (uint32_t)s * STAGE;
        int k0 = chunk * BKT;
        // (128 + 512) rows * 4 granules / 256 threads = 10 per thread
#pragma unroll
        for (int q = 0; q < 10; q++) {
            int g = tid + (q << 8);
            int r = g >> 2, gran = g & 3;
            if (r < BMT) {
                cp_async16(st + r * PITCH + gran * 16,
                           Ah + (size_t)(bm + r) * K + k0 + gran * 8);
            } else if (r < BMT + BNT) {
                int rb = r - BMT;
                cp_async16(st + BH_OFF + rb * PITCH + gran * 16,
                           Bh + (size_t)(bn + rb) * K + k0 + gran * 8);
            } else {
                int rb = r - BMT - BNT;
                cp_async16(st + BL_OFF + rb * PITCH + gran * 16,
                           Bl + (size_t)(bn + rb) * K + k0 + gran * 8);
            }
        }
    };

    float acc[4][8][4];
#pragma unroll
    for (int i = 0; i < 4; i++)
#pragma unroll
        for (int j = 0; j < 8; j++)
#pragma unroll
            for (int q = 0; q < 4; q++) acc[i][j][q] = 0.f;

    int mw = wid & 1, nw = wid >> 1;     // 2(m) x 4(n)
    uint32_t a_lane = (uint32_t)((mw * 64 + (lane & 15)) * PITCH + ((lane >> 4) << 4));
    uint32_t b_lane = (uint32_t)((nw * 64 + (lane & 7)) * PITCH + ((lane >> 3) << 4));

#pragma unroll
    for (int p = 0; p < NSTG - 1; p++) {
        load_chunk(p, p);
        asm volatile("cp.async.commit_group;");
    }

    for (int it = 0; it < NIT; it++) {
        int pf = it + NSTG - 1;
        if (pf < NIT) load_chunk(pf, pf % NSTG);
        asm volatile("cp.async.commit_group;");
        asm volatile("cp.async.wait_group %0;" :: "n"(NSTG - 1));
        __syncthreads();

        uint32_t st = sb + (uint32_t)(it % NSTG) * STAGE;

        uint32_t a[4][2][4];
#pragma unroll
        for (int i = 0; i < 4; i++)
#pragma unroll
            for (int s = 0; s < 2; s++)
                ldmx4(a[i][s], st + a_lane + (uint32_t)(i * 16 * PITCH + s * 32));

        // B in j-groups of 2 (16 live B regs)
#pragma unroll
        for (int jg = 0; jg < 8; jg += 2) {
            uint32_t bh[2][4], bl[2][4];
#pragma unroll
            for (int jj = 0; jj < 2; jj++)
                ldmx4(bh[jj], st + BH_OFF + b_lane + (uint32_t)((jg + jj) * 8 * PITCH));
#pragma unroll
            for (int jj = 0; jj < 2; jj++)
                ldmx4(bl[jj], st + BL_OFF + b_lane + (uint32_t)((jg + jj) * 8 * PITCH));
#pragma unroll
            for (int i = 0; i < 4; i++)
#pragma unroll
                for (int jj = 0; jj < 2; jj++) {
                    float* c = acc[i][jg + jj];
                    mma16816(c, a[i][0], bh[jj][0], bh[jj][1]);
                    mma16816(c, a[i][1], bh[jj][2], bh[jj][3]);
                    mma16816(c, a[i][0], bl[jj][0], bl[jj][1]);
                    mma16816(c, a[i][1], bl[jj][2], bl[jj][3]);
                }
        }
        __syncthreads();
    }

    int rg = lane >> 2;
    int cq = (lane & 3) * 2;
#pragma unroll
    for (int i = 0; i < 4; i++) {
#pragma unroll
        for (int j = 0; j < 8; j++) {
            int cn = bn + nw * 64 + j * 8 + cq;
            float bs0 = bias[cn], bs1 = bias[cn + 1];
#pragma unroll
            for (int h = 0; h < 2; h++) {
                int rm = bm + mw * 64 + i * 16 + rg + h * 8;
                float cur0 = acc[i][j][2 * h + 0] * INV_SW + bs0;
                float cur1 = acc[i][j][2 * h + 1] * INV_SW + bs1;
                *(float2*)(Cout + (size_t)rm * N + cn) = make_float2(cur0, cur1);
            }
        }
    }
}

// ------------------------- LIF scan over timesteps --------------------------
template<int OUTF>
__global__ void lif_scan_kernel(const float* __restrict__ cur,
                                void* __restrict__ spk, int NF,
                                const float* __restrict__ betas, int bidx,
                                const float* __restrict__ thrs,  int tidx) {
    size_t e = ((size_t)blockIdx.x * blockDim.x + threadIdx.x) * 4;
    float beta = clamp01(betas[bidx]);
    float thr  = thrs[tidx];
    float m0 = 0.f, m1 = 0.f, m2 = 0.f, m3 = 0.f;
    size_t step = (size_t)MS * NF;
#pragma unroll
    for (int t = 0; t < T_STEPS; t++) {
        float4 c = *(const float4*)(cur + t * step + e);
        float mn0 = beta * m0 + c.x - (m0 > thr ? thr : 0.f);
        float mn1 = beta * m1 + c.y - (m1 > thr ? thr : 0.f);
        float mn2 = beta * m2 + c.z - (m2 > thr ? thr : 0.f);
        float mn3 = beta * m3 + c.w - (m3 > thr ? thr : 0.f);
        float sp0 = (mn0 - thr) > 0.f ? 1.f : 0.f;
        float sp1 = (mn1 - thr) > 0.f ? 1.f : 0.f;
        float sp2 = (mn2 - thr) > 0.f ? 1.f : 0.f;
        float sp3 = (mn3 - thr) > 0.f ? 1.f : 0.f;
        if (OUTF == 0) {
            __half2* hp = (__half2*)((__half*)spk + t * step + e);
            hp[0] = __floats2half2_rn(sp0, sp1);
            hp[1] = __floats2half2_rn(sp2, sp3);
        } else {
            *(float4*)((float*)spk + t * step + e) = make_float4(sp0, sp1, sp2, sp3);
        }
        m0 = mn0; m1 = mn1; m2 = mn2; m3 = mn3;
    }
}

// ---------------------- readout matvec (parallel over t,b) ------------------
__global__ void out_matvec_kernel(const float* __restrict__ Wout,
                                  const float* __restrict__ bout) {
    __shared__ float red[4][256];
    int tb = blockIdx.x;           // t * BB + b
    int t = tb / BB, b = tb % BB;
    int tid = threadIdx.x;
    const float* s = g_spk2 + ((size_t)t * MS + b * RR) * H2F;
    const float4* W4 = (const float4*)Wout;
    float a0 = 0.f, a1 = 0.f, a2 = 0.f, a3 = 0.f;
    for (int k = tid; k < FOUT; k += 256) {
        float sv = s[k];
        float4 w = W4[k];
        a0 += sv * w.x; a1 += sv * w.y; a2 += sv * w.z; a3 += sv * w.w;
    }
    red[0][tid] = a0; red[1][tid] = a1; red[2][tid] = a2; red[3][tid] = a3;
    __syncthreads();
    for (int off = 128; off > 0; off >>= 1) {
        if (tid < off) {
#pragma unroll
            for (int q = 0; q < 4; q++) red[q][tid] += red[q][tid + off];
        }
        __syncthreads();
    }
    if (tid < 4)
        g_curout[(t * BB + b) * NCLS + tid] = red[tid][0] + bout[tid];
}

// ---------------------------- output LIF scan -------------------------------
__global__ void out_scan_kernel(const float* __restrict__ betas,
                                float* __restrict__ out) {
    int b = threadIdx.x;           // 32 threads
    float beta = clamp01(betas[3]);
    float m[4] = {0.f, 0.f, 0.f, 0.f};
    for (int t = 0; t < T_STEPS; t++) {
#pragma unroll
        for (int n = 0; n < 4; n++) {
            float cur = g_curout[(t * BB + b) * NCLS + n];
            float mn = beta * m[n] + cur - (m[n] > 1.0f ? 1.0f : 0.f);
            m[n] = mn;
            out[t * BB * NCLS + b * NCLS + n] = (mn - 1.0f) > 0.f ? 1.f : 0.f;
        }
    }
}

// ------------------------------- launch -------------------------------------
extern "C" void kernel_launch(void* const* d_in, const int* in_sizes, int n_in,
                              void* d_out, int out_size) {
    const float* x     = (const float*)d_in[0];
    const float* W_in  = (const float*)d_in[1];
    const float* b_in  = (const float*)d_in[2];
    const float* W_h1  = (const float*)d_in[3];
    const float* b_h1  = (const float*)d_in[4];
    const float* W_h2  = (const float*)d_in[5];
    const float* b_h2  = (const float*)d_in[6];
    const float* W_out = (const float*)d_in[7];
    const float* b_out = (const float*)d_in[8];
    const float* betas = (const float*)d_in[9];
    const float* thrs  = (const float*)d_in[10];
    float* out = (float*)d_out;

    __half *p_feat_h, *p_feat_l, *p_spkin, *p_spk1;
    __half *p_Winh, *p_Winl, *p_Wh1h, *p_Wh1l, *p_Wh2h, *p_Wh2l;
    float *p_cur, *p_spk2;
    cudaGetSymbolAddress((void**)&p_feat_h, g_feat_h);
    cudaGetSymbolAddress((void**)&p_feat_l, g_feat_l);
    cudaGetSymbolAddress((void**)&p_cur,    g_cur);
    cudaGetSymbolAddress((void**)&p_spkin,  g_spkin_h);
    cudaGetSymbolAddress((void**)&p_spk1,   g_spk1_h);
    cudaGetSymbolAddress((void**)&p_spk2,   g_spk2);
    cudaGetSymbolAddress((void**)&p_Winh,   g_Win_h);
    cudaGetSymbolAddress((void**)&p_Winl,   g_Win_l);
    cudaGetSymbolAddress((void**)&p_Wh1h,   g_Wh1_h);
    cudaGetSymbolAddress((void**)&p_Wh1l,   g_Wh1_l);
    cudaGetSymbolAddress((void**)&p_Wh2h,   g_Wh2_h);
    cudaGetSymbolAddress((void**)&p_Wh2l,   g_Wh2_l);

    const int SMEM1 = 3 * (2 * 128 * PITCH + 2 * 64 * PITCH);   // 92160
    const int SMEMW = 3 * (128 * PITCH + 2 * 256 * PITCH);      // 153600
    cudaFuncSetAttribute((const void*)hgemm_kernel<true>,
                         cudaFuncAttributeMaxDynamicSharedMemorySize, SMEM1);
    cudaFuncSetAttribute((const void*)hgemm_wide_kernel,
                         cudaFuncAttributeMaxDynamicSharedMemorySize, SMEMW);

    pool_kernel<<<T_STEPS * BB * CC * TPP, 256>>>(x);                       // 0
    split_tr_kernel<<<dim3(H0F / 32, D_INF / 32), dim3(32, 8)>>>(
        W_in, p_Winh, p_Winl, D_INF, H0F);                                   // 1
    split_tr_kernel<<<dim3(H1F / 32, H0F / 32),  dim3(32, 8)>>>(
        W_h1, p_Wh1h, p_Wh1l, H0F, H1F);                                     // 2

    // GEMM1: cur_in = feat @ W_in + b_in   [14336, 2048] (launch idx 3: ncu)
    hgemm_kernel<true><<<dim3(H0F / 64, M_ALL / 128), 256, SMEM1>>>(
        M_ALL, H0F, D_INF, p_feat_h, p_feat_l, p_Winh, p_Winl, b_in, p_cur);

    lif_scan_kernel<0><<<(MS * H0F / 4) / 256, 256>>>(
        p_cur, p_spkin, H0F, betas, 0, thrs, 0);

    split_tr_kernel<<<dim3(H2F / 32, H1F / 32),  dim3(32, 8)>>>(
        W_h2, p_Wh2h, p_Wh2l, H1F, H2F);

    // GEMM2 (wide): cur1 = spk_in @ W_h1 + b_h1  [14336, 2048] grid (8,112)
    hgemm_wide_kernel<<<dim3(H1F / 256, M_ALL / 128), 256, SMEMW>>>(
        M_ALL, H1F, H0F, p_spkin, p_Wh1h, p_Wh1l, b_h1, p_cur);

    lif_scan_kernel<0><<<(MS * H1F / 4) / 256, 256>>>(
        p_cur, p_spk1, H1F, betas, 1, thrs, 1);

    // GEMM3 (wide): cur2 = spk1 @ W_h2 + b_h2   [14336, 1024] grid (4,112)
    hgemm_wide_kernel<<<dim3(H2F / 256, M_ALL / 128), 256, SMEMW>>>(
        M_ALL, H2F, H1F, p_spk1, p_Wh2h, p_Wh2l, b_h2, p_cur);

    lif_scan_kernel<1><<<(MS * H2F / 4) / 256, 256>>>(
        p_cur, p_spk2, H2F, betas, 2, thrs, 2);

    // readout: parallel matvec over (t,b), then tiny LIF scan
    out_matvec_kernel<<<T_STEPS * BB, 256>>>(W_out, b_out);
    out_scan_kernel<<<1, BB>>>(betas, out);
}

// round 15
// speedup vs baseline: 1.5894x; 1.0006x over previous
#include <cuda_runtime.h>
#include <cuda_fp16.h>
#include <stdint.h>

// ---------------------------------------------------------------------------
// SNN: pool -> fc_in -> 3x LIF layers -> readout, T=8.
// Split-precision fp16 HMMA, exact for spikes. Time-batched GEMMs.
// R15: GEMM1 also moves to the 64x64 warp tile (wide split-A variant),
// same per-output MMA order as before (bit-identical outputs).
// ---------------------------------------------------------------------------

#define T_STEPS 8
#define BB      32
#define CC      4
#define CHUNK   29
#define HH      64
#define WW      64
#define TPP     14
#define HP      32
#define WP      32
#define RR      56
#define D_INF   1024
#define H0F     2048
#define H1F     2048
#define H2F     1024
#define NCLS    4
#define MS      (BB*RR)         // 1792
#define M_ALL   (T_STEPS*MS)    // 14336
#define FOUT    (RR*H2F)        // 57344

#define SCALE_W 32.0f
#define INV_SW  (1.0f/32.0f)

#define BKT   32
#define PITCH 80

// ------------------------- static scratch ----------------------------------
__device__ __half g_feat_h[(size_t)M_ALL * D_INF];
__device__ __half g_feat_l[(size_t)M_ALL * D_INF];
__device__ float  g_cur   [(size_t)M_ALL * H0F];
__device__ __half g_spkin_h[(size_t)M_ALL * H0F];
__device__ __half g_spk1_h [(size_t)M_ALL * H1F];
__device__ float  g_spk2   [(size_t)M_ALL * H2F];
__device__ float  g_curout [T_STEPS * BB * NCLS];
__device__ __half g_Win_h[(size_t)H0F * D_INF];
__device__ __half g_Win_l[(size_t)H0F * D_INF];
__device__ __half g_Wh1_h[(size_t)H1F * H0F];
__device__ __half g_Wh1_l[(size_t)H1F * H0F];
__device__ __half g_Wh2_h[(size_t)H2F * H1F];
__device__ __half g_Wh2_l[(size_t)H2F * H1F];

__device__ __forceinline__ float clamp01(float v) {
    return fminf(fmaxf(v, 0.0f), 1.0f);
}
__device__ __forceinline__ uint32_t smem_u32(const void* p) {
    uint32_t a;
    asm("{ .reg .u64 t; cvta.to.shared.u64 t, %1; cvt.u32.u64 %0, t; }" : "=r"(a) : "l"(p));
    return a;
}
__device__ __forceinline__ void cp_async16(uint32_t dst, const void* src) {
    asm volatile("cp.async.cg.shared.global [%0], [%1], 16;" :: "r"(dst), "l"(src));
}
__device__ __forceinline__ void ldmx4(uint32_t* r, uint32_t addr) {
    asm volatile("ldmatrix.sync.aligned.m8n8.x4.shared.b16 {%0,%1,%2,%3}, [%4];"
        : "=r"(r[0]), "=r"(r[1]), "=r"(r[2]), "=r"(r[3]) : "r"(addr));
}
__device__ __forceinline__ void mma16816(float* c, const uint32_t* a,
                                         uint32_t b0, uint32_t b1) {
    asm volatile(
        "mma.sync.aligned.m16n8k16.row.col.f32.f16.f16.f32 "
        "{%0,%1,%2,%3}, {%4,%5,%6,%7}, {%8,%9}, {%0,%1,%2,%3};"
        : "+f"(c[0]), "+f"(c[1]), "+f"(c[2]), "+f"(c[3])
        : "r"(a[0]), "r"(a[1]), "r"(a[2]), "r"(a[3]), "r"(b0), "r"(b1));
}

// ------------------------- weight split + transpose -------------------------
__global__ void split_tr_kernel(const float* __restrict__ W,
                                __half* __restrict__ Th, __half* __restrict__ Tl,
                                int K, int N) {
    __shared__ float tile[32][33];
    int n0 = blockIdx.x * 32, k0 = blockIdx.y * 32;
    int tx = threadIdx.x, ty = threadIdx.y;   // 32 x 8
#pragma unroll
    for (int j = 0; j < 32; j += 8)
        tile[ty + j][tx] = W[(size_t)(k0 + ty + j) * N + n0 + tx];
    __syncthreads();
#pragma unroll
    for (int j = 0; j < 32; j += 8) {
        float w = tile[tx][ty + j] * SCALE_W;
        __half hi = __float2half_rn(w);
        __half lo = __float2half_rn(w - __half2float(hi));
        size_t o = (size_t)(n0 + ty + j) * K + k0 + tx;
        Th[o] = hi; Tl[o] = lo;
    }
}

// ------------------------------- avg pool 3d --------------------------------
__global__ void pool_kernel(const float* __restrict__ x) {
    int blk = blockIdx.x;
    int tp = blk % TPP;
    int c  = (blk / TPP) % CC;
    int b  = (blk / (TPP * CC)) % BB;
    int t  =  blk / (TPP * CC * BB);
    int f0 = t * CHUNK + tp * 2;
    const float* xb = x + ((size_t)(b * CC + c) * 232 + f0) * (HH * WW);
    size_t obase = ((size_t)((t * BB + b) * RR + (c * TPP + tp))) * D_INF;
    __half* oh = g_feat_h + obase;
    __half* ol = g_feat_l + obase;
    for (int d = threadIdx.x; d < HP * WP; d += blockDim.x) {
        int hp = d >> 5, wp = d & 31;
        const float* p = xb + (hp * 2) * WW + wp * 2;
        float s = 0.f;
#pragma unroll
        for (int kd = 0; kd < 3; kd++) {
            const float* pf = p + kd * (HH * WW);
            float2 a0 = *(const float2*)pf;
            float2 a1 = *(const float2*)(pf + WW);
            s += (a0.x + a0.y) + (a1.x + a1.y);
        }
        float v = s / 12.0f;
        __half hi = __float2half_rn(v);
        __half lo = __float2half_rn(v - __half2float(hi));
        oh[d] = hi; ol[d] = lo;
    }
}

// ------------- HMMA GEMM, 64x64 warp tile, split-A (GEMM1) ------------------
// CTA 128(m) x 256(n); warps 2(m) x 4(n); 3-stage cp.async; occ 1.
// Per chunk, per output: a.bh, a.bl, al.bh  (same K-order as before).
__global__ void __launch_bounds__(256, 1) hgemm_wide_split_kernel(
    int M, int N, int K,
    const __half* __restrict__ Ah, const __half* __restrict__ Al,
    const __half* __restrict__ Bh, const __half* __restrict__ Bl,
    const float* __restrict__ bias,
    float* __restrict__ Cout)
{
    extern __shared__ char smem[];
    const int BMT = 128, BNT = 256, NSTG = 3;
    const int A_TILE = BMT * PITCH;     // 10240
    const int B_TILE = BNT * PITCH;     // 20480
    const int AL_OFF = A_TILE;
    const int BH_OFF = 2 * A_TILE;
    const int BL_OFF = BH_OFF + B_TILE;
    const int STAGE  = BL_OFF + B_TILE; // 61440
    uint32_t sb = smem_u32(smem);

    int tid  = threadIdx.x;
    int wid  = tid >> 5, lane = tid & 31;
    const int bm = blockIdx.y * BMT;
    const int bn = blockIdx.x * BNT;
    const int NIT = K / BKT;

    auto load_chunk = [&](int chunk, int s) {
        uint32_t st = sb + (uint32_t)s * STAGE;
        int k0 = chunk * BKT;
        // (128 + 128 + 256 + 256) rows * 4 granules / 256 threads = 12
#pragma unroll
        for (int q = 0; q < 12; q++) {
            int g = tid + (q << 8);
            int r = g >> 2, gran = g & 3;
            if (r < BMT) {
                cp_async16(st + r * PITCH + gran * 16,
                           Ah + (size_t)(bm + r) * K + k0 + gran * 8);
            } else if (r < 2 * BMT) {
                int ra = r - BMT;
                cp_async16(st + AL_OFF + ra * PITCH + gran * 16,
                           Al + (size_t)(bm + ra) * K + k0 + gran * 8);
            } else if (r < 2 * BMT + BNT) {
                int rb = r - 2 * BMT;
                cp_async16(st + BH_OFF + rb * PITCH + gran * 16,
                           Bh + (size_t)(bn + rb) * K + k0 + gran * 8);
            } else {
                int rb = r - 2 * BMT - BNT;
                cp_async16(st + BL_OFF + rb * PITCH + gran * 16,
                           Bl + (size_t)(bn + rb) * K + k0 + gran * 8);
            }
        }
    };

    float acc[4][8][4];
#pragma unroll
    for (int i = 0; i < 4; i++)
#pragma unroll
        for (int j = 0; j < 8; j++)
#pragma unroll
            for (int q = 0; q < 4; q++) acc[i][j][q] = 0.f;

    int mw = wid & 1, nw = wid >> 1;     // 2(m) x 4(n)
    uint32_t a_lane = (uint32_t)((mw * 64 + (lane & 15)) * PITCH + ((lane >> 4) << 4));
    uint32_t b_lane = (uint32_t)((nw * 64 + (lane & 7)) * PITCH + ((lane >> 3) << 4));

#pragma unroll
    for (int p = 0; p < NSTG - 1; p++) {
        load_chunk(p, p);
        asm volatile("cp.async.commit_group;");
    }

    for (int it = 0; it < NIT; it++) {
        int pf = it + NSTG - 1;
        if (pf < NIT) load_chunk(pf, pf % NSTG);
        asm volatile("cp.async.commit_group;");
        asm volatile("cp.async.wait_group %0;" :: "n"(NSTG - 1));
        __syncthreads();

        uint32_t st = sb + (uint32_t)(it % NSTG) * STAGE;

        uint32_t a[4][2][4], al[4][2][4];
#pragma unroll
        for (int i = 0; i < 4; i++)
#pragma unroll
            for (int s = 0; s < 2; s++)
                ldmx4(a[i][s], st + a_lane + (uint32_t)(i * 16 * PITCH + s * 32));
#pragma unroll
        for (int i = 0; i < 4; i++)
#pragma unroll
            for (int s = 0; s < 2; s++)
                ldmx4(al[i][s], st + AL_OFF + a_lane + (uint32_t)(i * 16 * PITCH + s * 32));

#pragma unroll
        for (int jg = 0; jg < 8; jg += 2) {
            uint32_t bh[2][4], bl[2][4];
#pragma unroll
            for (int jj = 0; jj < 2; jj++)
                ldmx4(bh[jj], st + BH_OFF + b_lane + (uint32_t)((jg + jj) * 8 * PITCH));
#pragma unroll
            for (int jj = 0; jj < 2; jj++)
                ldmx4(bl[jj], st + BL_OFF + b_lane + (uint32_t)((jg + jj) * 8 * PITCH));
#pragma unroll
            for (int i = 0; i < 4; i++)
#pragma unroll
                for (int jj = 0; jj < 2; jj++) {
                    float* c = acc[i][jg + jj];
                    mma16816(c, a[i][0], bh[jj][0], bh[jj][1]);
                    mma16816(c, a[i][1], bh[jj][2], bh[jj][3]);
                    mma16816(c, a[i][0], bl[jj][0], bl[jj][1]);
                    mma16816(c, a[i][1], bl[jj][2], bl[jj][3]);
                }
#pragma unroll
            for (int i = 0; i < 4; i++)
#pragma unroll
                for (int jj = 0; jj < 2; jj++) {
                    float* c = acc[i][jg + jj];
                    mma16816(c, al[i][0], bh[jj][0], bh[jj][1]);
                    mma16816(c, al[i][1], bh[jj][2], bh[jj][3]);
                }
        }
        __syncthreads();
    }

    int rg = lane >> 2;
    int cq = (lane & 3) * 2;
#pragma unroll
    for (int i = 0; i < 4; i++) {
#pragma unroll
        for (int j = 0; j < 8; j++) {
            int cn = bn + nw * 64 + j * 8 + cq;
            float bs0 = bias[cn], bs1 = bias[cn + 1];
#pragma unroll
            for (int h = 0; h < 2; h++) {
                int rm = bm + mw * 64 + i * 16 + rg + h * 8;
                float cur0 = acc[i][j][2 * h + 0] * INV_SW + bs0;
                float cur1 = acc[i][j][2 * h + 1] * INV_SW + bs1;
                *(float2*)(Cout + (size_t)rm * N + cn) = make_float2(cur0, cur1);
            }
        }
    }
}

// ------------------- HMMA GEMM, 64x64 warp tile (GEMM2/3) -------------------
__global__ void __launch_bounds__(256, 1) hgemm_wide_kernel(
    int M, int N, int K,
    const __half* __restrict__ Ah,
    const __half* __restrict__ Bh, const __half* __restrict__ Bl,
    const float* __restrict__ bias,
    float* __restrict__ Cout)
{
    extern __shared__ char smem[];
    const int BMT = 128, BNT = 256, NSTG = 3;
    const int A_TILE = BMT * PITCH;     // 10240
    const int B_TILE = BNT * PITCH;     // 20480
    const int BH_OFF = A_TILE;
    const int BL_OFF = BH_OFF + B_TILE;
    const int STAGE  = BL_OFF + B_TILE; // 51200
    uint32_t sb = smem_u32(smem);

    int tid  = threadIdx.x;
    int wid  = tid >> 5, lane = tid & 31;
    const int bm = blockIdx.y * BMT;
    const int bn = blockIdx.x * BNT;
    const int NIT = K / BKT;

    auto load_chunk = [&](int chunk, int s) {
        uint32_t st = sb + (uint32_t)s * STAGE;
        int k0 = chunk * BKT;
#pragma unroll
        for (int q = 0; q < 10; q++) {
            int g = tid + (q << 8);
            int r = g >> 2, gran = g & 3;
            if (r < BMT) {
                cp_async16(st + r * PITCH + gran * 16,
                           Ah + (size_t)(bm + r) * K + k0 + gran * 8);
            } else if (r < BMT + BNT) {
                int rb = r - BMT;
                cp_async16(st + BH_OFF + rb * PITCH + gran * 16,
                           Bh + (size_t)(bn + rb) * K + k0 + gran * 8);
            } else {
                int rb = r - BMT - BNT;
                cp_async16(st + BL_OFF + rb * PITCH + gran * 16,
                           Bl + (size_t)(bn + rb) * K + k0 + gran * 8);
            }
        }
    };

    float acc[4][8][4];
#pragma unroll
    for (int i = 0; i < 4; i++)
#pragma unroll
        for (int j = 0; j < 8; j++)
#pragma unroll
            for (int q = 0; q < 4; q++) acc[i][j][q] = 0.f;

    int mw = wid & 1, nw = wid >> 1;
    uint32_t a_lane = (uint32_t)((mw * 64 + (lane & 15)) * PITCH + ((lane >> 4) << 4));
    uint32_t b_lane = (uint32_t)((nw * 64 + (lane & 7)) * PITCH + ((lane >> 3) << 4));

#pragma unroll
    for (int p = 0; p < NSTG - 1; p++) {
        load_chunk(p, p);
        asm volatile("cp.async.commit_group;");
    }

    for (int it = 0; it < NIT; it++) {
        int pf = it + NSTG - 1;
        if (pf < NIT) load_chunk(pf, pf % NSTG);
        asm volatile("cp.async.commit_group;");
        asm volatile("cp.async.wait_group %0;" :: "n"(NSTG - 1));
        __syncthreads();

        uint32_t st = sb + (uint32_t)(it % NSTG) * STAGE;

        uint32_t a[4][2][4];
#pragma unroll
        for (int i = 0; i < 4; i++)
#pragma unroll
            for (int s = 0; s < 2; s++)
                ldmx4(a[i][s], st + a_lane + (uint32_t)(i * 16 * PITCH + s * 32));

#pragma unroll
        for (int jg = 0; jg < 8; jg += 2) {
            uint32_t bh[2][4], bl[2][4];
#pragma unroll
            for (int jj = 0; jj < 2; jj++)
                ldmx4(bh[jj], st + BH_OFF + b_lane + (uint32_t)((jg + jj) * 8 * PITCH));
#pragma unroll
            for (int jj = 0; jj < 2; jj++)
                ldmx4(bl[jj], st + BL_OFF + b_lane + (uint32_t)((jg + jj) * 8 * PITCH));
#pragma unroll
            for (int i = 0; i < 4; i++)
#pragma unroll
                for (int jj = 0; jj < 2; jj++) {
                    float* c = acc[i][jg + jj];
                    mma16816(c, a[i][0], bh[jj][0], bh[jj][1]);
                    mma16816(c, a[i][1], bh[jj][2], bh[jj][3]);
                    mma16816(c, a[i][0], bl[jj][0], bl[jj][1]);
                    mma16816(c, a[i][1], bl[jj][2], bl[jj][3]);
                }
        }
        __syncthreads();
    }

    int rg = lane >> 2;
    int cq = (lane & 3) * 2;
#pragma unroll
    for (int i = 0; i < 4; i++) {
#pragma unroll
        for (int j = 0; j < 8; j++) {
            int cn = bn + nw * 64 + j * 8 + cq;
            float bs0 = bias[cn], bs1 = bias[cn + 1];
#pragma unroll
            for (int h = 0; h < 2; h++) {
                int rm = bm + mw * 64 + i * 16 + rg + h * 8;
                float cur0 = acc[i][j][2 * h + 0] * INV_SW + bs0;
                float cur1 = acc[i][j][2 * h + 1] * INV_SW + bs1;
                *(float2*)(Cout + (size_t)rm * N + cn) = make_float2(cur0, cur1);
            }
        }
    }
}

// ------------------------- LIF scan over timesteps --------------------------
template<int OUTF>
__global__ void lif_scan_kernel(const float* __restrict__ cur,
                                void* __restrict__ spk, int NF,
                                const float* __restrict__ betas, int bidx,
                                const float* __restrict__ thrs,  int tidx) {
    size_t e = ((size_t)blockIdx.x * blockDim.x + threadIdx.x) * 4;
    float beta = clamp01(betas[bidx]);
    float thr  = thrs[tidx];
    float m0 = 0.f, m1 = 0.f, m2 = 0.f, m3 = 0.f;
    size_t step = (size_t)MS * NF;
#pragma unroll
    for (int t = 0; t < T_STEPS; t++) {
        float4 c = *(const float4*)(cur + t * step + e);
        float mn0 = beta * m0 + c.x - (m0 > thr ? thr : 0.f);
        float mn1 = beta * m1 + c.y - (m1 > thr ? thr : 0.f);
        float mn2 = beta * m2 + c.z - (m2 > thr ? thr : 0.f);
        float mn3 = beta * m3 + c.w - (m3 > thr ? thr : 0.f);
        float sp0 = (mn0 - thr) > 0.f ? 1.f : 0.f;
        float sp1 = (mn1 - thr) > 0.f ? 1.f : 0.f;
        float sp2 = (mn2 - thr) > 0.f ? 1.f : 0.f;
        float sp3 = (mn3 - thr) > 0.f ? 1.f : 0.f;
        if (OUTF == 0) {
            __half2* hp = (__half2*)((__half*)spk + t * step + e);
            hp[0] = __floats2half2_rn(sp0, sp1);
            hp[1] = __floats2half2_rn(sp2, sp3);
        } else {
            *(float4*)((float*)spk + t * step + e) = make_float4(sp0, sp1, sp2, sp3);
        }
        m0 = mn0; m1 = mn1; m2 = mn2; m3 = mn3;
    }
}

// ---------------------- readout matvec (parallel over t,b) ------------------
__global__ void out_matvec_kernel(const float* __restrict__ Wout,
                                  const float* __restrict__ bout) {
    __shared__ float red[4][256];
    int tb = blockIdx.x;           // t * BB + b
    int t = tb / BB, b = tb % BB;
    int tid = threadIdx.x;
    const float* s = g_spk2 + ((size_t)t * MS + b * RR) * H2F;
    const float4* W4 = (const float4*)Wout;
    float a0 = 0.f, a1 = 0.f, a2 = 0.f, a3 = 0.f;
    for (int k = tid; k < FOUT; k += 256) {
        float sv = s[k];
        float4 w = W4[k];
        a0 += sv * w.x; a1 += sv * w.y; a2 += sv * w.z; a3 += sv * w.w;
    }
    red[0][tid] = a0; red[1][tid] = a1; red[2][tid] = a2; red[3][tid] = a3;
    __syncthreads();
    for (int off = 128; off > 0; off >>= 1) {
        if (tid < off) {
#pragma unroll
            for (int q = 0; q < 4; q++) red[q][tid] += red[q][tid + off];
        }
        __syncthreads();
    }
    if (tid < 4)
        g_curout[(t * BB + b) * NCLS + tid] = red[tid][0] + bout[tid];
}

// ---------------------------- output LIF scan -------------------------------
__global__ void out_scan_kernel(const float* __restrict__ betas,
                                float* __restrict__ out) {
    int b = threadIdx.x;           // 32 threads
    float beta = clamp01(betas[3]);
    float m[4] = {0.f, 0.f, 0.f, 0.f};
    for (int t = 0; t < T_STEPS; t++) {
#pragma unroll
        for (int n = 0; n < 4; n++) {
            float cur = g_curout[(t * BB + b) * NCLS + n];
            float mn = beta * m[n] + cur - (m[n] > 1.0f ? 1.0f : 0.f);
            m[n] = mn;
            out[t * BB * NCLS + b * NCLS + n] = (mn - 1.0f) > 0.f ? 1.f : 0.f;
        }
    }
}

// ------------------------------- launch -------------------------------------
extern "C" void kernel_launch(void* const* d_in, const int* in_sizes, int n_in,
                              void* d_out, int out_size) {
    const float* x     = (const float*)d_in[0];
    const float* W_in  = (const float*)d_in[1];
    const float* b_in  = (const float*)d_in[2];
    const float* W_h1  = (const float*)d_in[3];
    const float* b_h1  = (const float*)d_in[4];
    const float* W_h2  = (const float*)d_in[5];
    const float* b_h2  = (const float*)d_in[6];
    const float* W_out = (const float*)d_in[7];
    const float* b_out = (const float*)d_in[8];
    const float* betas = (const float*)d_in[9];
    const float* thrs  = (const float*)d_in[10];
    float* out = (float*)d_out;

    __half *p_feat_h, *p_feat_l, *p_spkin, *p_spk1;
    __half *p_Winh, *p_Winl, *p_Wh1h, *p_Wh1l, *p_Wh2h, *p_Wh2l;
    float *p_cur, *p_spk2;
    cudaGetSymbolAddress((void**)&p_feat_h, g_feat_h);
    cudaGetSymbolAddress((void**)&p_feat_l, g_feat_l);
    cudaGetSymbolAddress((void**)&p_cur,    g_cur);
    cudaGetSymbolAddress((void**)&p_spkin,  g_spkin_h);
    cudaGetSymbolAddress((void**)&p_spk1,   g_spk1_h);
    cudaGetSymbolAddress((void**)&p_spk2,   g_spk2);
    cudaGetSymbolAddress((void**)&p_Winh,   g_Win_h);
    cudaGetSymbolAddress((void**)&p_Winl,   g_Win_l);
    cudaGetSymbolAddress((void**)&p_Wh1h,   g_Wh1_h);
    cudaGetSymbolAddress((void**)&p_Wh1l,   g_Wh1_l);
    cudaGetSymbolAddress((void**)&p_Wh2h,   g_Wh2_h);
    cudaGetSymbolAddress((void**)&p_Wh2l,   g_Wh2_l);

    const int SMEMS = 3 * (2 * 128 * PITCH + 2 * 256 * PITCH);  // 184320
    const int SMEMW = 3 * (128 * PITCH + 2 * 256 * PITCH);      // 153600
    cudaFuncSetAttribute((const void*)hgemm_wide_split_kernel,
                         cudaFuncAttributeMaxDynamicSharedMemorySize, SMEMS);
    cudaFuncSetAttribute((const void*)hgemm_wide_kernel,
                         cudaFuncAttributeMaxDynamicSharedMemorySize, SMEMW);

    pool_kernel<<<T_STEPS * BB * CC * TPP, 256>>>(x);                       // 0
    split_tr_kernel<<<dim3(H0F / 32, D_INF / 32), dim3(32, 8)>>>(
        W_in, p_Winh, p_Winl, D_INF, H0F);                                   // 1
    split_tr_kernel<<<dim3(H1F / 32, H0F / 32),  dim3(32, 8)>>>(
        W_h1, p_Wh1h, p_Wh1l, H0F, H1F);                                     // 2

    // GEMM1 (wide split-A): cur_in = feat @ W_in + b_in  [14336, 2048]
    hgemm_wide_split_kernel<<<dim3(H0F / 256, M_ALL / 128), 256, SMEMS>>>(   // 3
        M_ALL, H0F, D_INF, p_feat_h, p_feat_l, p_Winh, p_Winl, b_in, p_cur);

    lif_scan_kernel<0><<<(MS * H0F / 4) / 256, 256>>>(
        p_cur, p_spkin, H0F, betas, 0, thrs, 0);

    split_tr_kernel<<<dim3(H2F / 32, H1F / 32),  dim3(32, 8)>>>(
        W_h2, p_Wh2h, p_Wh2l, H1F, H2F);

    // GEMM2 (wide): cur1 = spk_in @ W_h1 + b_h1  [14336, 2048]
    hgemm_wide_kernel<<<dim3(H1F / 256, M_ALL / 128), 256, SMEMW>>>(
        M_ALL, H1F, H0F, p_spkin, p_Wh1h, p_Wh1l, b_h1, p_cur);

    lif_scan_kernel<0><<<(MS * H1F / 4) / 256, 256>>>(
        p_cur, p_spk1, H1F, betas, 1, thrs, 1);

    // GEMM3 (wide): cur2 = spk1 @ W_h2 + b_h2   [14336, 1024]
    hgemm_wide_kernel<<<dim3(H2F / 256, M_ALL / 128), 256, SMEMW>>>(
        M_ALL, H2F, H1F, p_spk1, p_Wh2h, p_Wh2l, b_h2, p_cur);

    lif_scan_kernel<1><<<(MS * H2F / 4) / 256, 256>>>(
        p_cur, p_spk2, H2F, betas, 2, thrs, 2);

    out_matvec_kernel<<<T_STEPS * BB, 256>>>(W_out, b_out);
    out_scan_kernel<<<1, BB>>>(betas, out);
}

// round 16
// speedup vs baseline: 1.8323x; 1.1529x over previous
#include <cuda_runtime.h>
#include <cuda_fp16.h>
#include <stdint.h>

// ---------------------------------------------------------------------------
// SNN: pool -> fc_in -> 3x LIF layers -> readout, T=8.
// Split-precision fp16 HMMA, exact for spikes. Time-batched GEMMs.
// R16: BKT=64 / NSTG=2 mainloop (half the barriers, 2x straight-line ILP
// window, shorter fragment live ranges). Bit-identical MMA order per output.
// ---------------------------------------------------------------------------

#define T_STEPS 8
#define BB      32
#define CC      4
#define CHUNK   29
#define HH      64
#define WW      64
#define TPP     14
#define HP      32
#define WP      32
#define RR      56
#define D_INF   1024
#define H0F     2048
#define H1F     2048
#define H2F     1024
#define NCLS    4
#define MS      (BB*RR)         // 1792
#define M_ALL   (T_STEPS*MS)    // 14336
#define FOUT    (RR*H2F)        // 57344

#define SCALE_W 32.0f
#define INV_SW  (1.0f/32.0f)

#define BKT2  64                 // K elems per chunk
#define P2    144                // bytes per 128B k-row (+16 pad)

// ------------------------- static scratch ----------------------------------
__device__ __half g_feat_h[(size_t)M_ALL * D_INF];
__device__ __half g_feat_l[(size_t)M_ALL * D_INF];
__device__ float  g_cur   [(size_t)M_ALL * H0F];
__device__ __half g_spkin_h[(size_t)M_ALL * H0F];
__device__ __half g_spk1_h [(size_t)M_ALL * H1F];
__device__ __half g_spk2_h [(size_t)M_ALL * H2F];
__device__ float  g_curout [T_STEPS * BB * NCLS];
__device__ __half g_Win_h[(size_t)H0F * D_INF];
__device__ __half g_Win_l[(size_t)H0F * D_INF];
__device__ __half g_Wh1_h[(size_t)H1F * H0F];
__device__ __half g_Wh1_l[(size_t)H1F * H0F];
__device__ __half g_Wh2_h[(size_t)H2F * H1F];
__device__ __half g_Wh2_l[(size_t)H2F * H1F];

__device__ __forceinline__ float clamp01(float v) {
    return fminf(fmaxf(v, 0.0f), 1.0f);
}
__device__ __forceinline__ uint32_t smem_u32(const void* p) {
    uint32_t a;
    asm("{ .reg .u64 t; cvta.to.shared.u64 t, %1; cvt.u32.u64 %0, t; }" : "=r"(a) : "l"(p));
    return a;
}
__device__ __forceinline__ void cp_async16(uint32_t dst, const void* src) {
    asm volatile("cp.async.cg.shared.global [%0], [%1], 16;" :: "r"(dst), "l"(src));
}
__device__ __forceinline__ void ldmx4(uint32_t* r, uint32_t addr) {
    asm volatile("ldmatrix.sync.aligned.m8n8.x4.shared.b16 {%0,%1,%2,%3}, [%4];"
        : "=r"(r[0]), "=r"(r[1]), "=r"(r[2]), "=r"(r[3]) : "r"(addr));
}
__device__ __forceinline__ void mma16816(float* c, const uint32_t* a,
                                         uint32_t b0, uint32_t b1) {
    asm volatile(
        "mma.sync.aligned.m16n8k16.row.col.f32.f16.f16.f32 "
        "{%0,%1,%2,%3}, {%4,%5,%6,%7}, {%8,%9}, {%0,%1,%2,%3};"
        : "+f"(c[0]), "+f"(c[1]), "+f"(c[2]), "+f"(c[3])
        : "r"(a[0]), "r"(a[1]), "r"(a[2]), "r"(a[3]), "r"(b0), "r"(b1));
}

// ------------------------- weight split + transpose -------------------------
__global__ void split_tr_kernel(const float* __restrict__ W,
                                __half* __restrict__ Th, __half* __restrict__ Tl,
                                int K, int N) {
    __shared__ float tile[32][33];
    int n0 = blockIdx.x * 32, k0 = blockIdx.y * 32;
    int tx = threadIdx.x, ty = threadIdx.y;   // 32 x 8
#pragma unroll
    for (int j = 0; j < 32; j += 8)
        tile[ty + j][tx] = W[(size_t)(k0 + ty + j) * N + n0 + tx];
    __syncthreads();
#pragma unroll
    for (int j = 0; j < 32; j += 8) {
        float w = tile[tx][ty + j] * SCALE_W;
        __half hi = __float2half_rn(w);
        __half lo = __float2half_rn(w - __half2float(hi));
        size_t o = (size_t)(n0 + ty + j) * K + k0 + tx;
        Th[o] = hi; Tl[o] = lo;
    }
}

// ------------------------------- avg pool 3d --------------------------------
__global__ void pool_kernel(const float* __restrict__ x) {
    int blk = blockIdx.x;
    int tp = blk % TPP;
    int c  = (blk / TPP) % CC;
    int b  = (blk / (TPP * CC)) % BB;
    int t  =  blk / (TPP * CC * BB);
    int f0 = t * CHUNK + tp * 2;
    const float* xb = x + ((size_t)(b * CC + c) * 232 + f0) * (HH * WW);
    size_t obase = ((size_t)((t * BB + b) * RR + (c * TPP + tp))) * D_INF;
    __half* oh = g_feat_h + obase;
    __half* ol = g_feat_l + obase;
    for (int d = threadIdx.x; d < HP * WP; d += blockDim.x) {
        int hp = d >> 5, wp = d & 31;
        const float* p = xb + (hp * 2) * WW + wp * 2;
        float s = 0.f;
#pragma unroll
        for (int kd = 0; kd < 3; kd++) {
            const float* pf = p + kd * (HH * WW);
            float2 a0 = *(const float2*)pf;
            float2 a1 = *(const float2*)(pf + WW);
            s += (a0.x + a0.y) + (a1.x + a1.y);
        }
        float v = s / 12.0f;
        __half hi = __float2half_rn(v);
        __half lo = __float2half_rn(v - __half2float(hi));
        oh[d] = hi; ol[d] = lo;
    }
}

// ------------- HMMA GEMM: 128x256 CTA, 64x64 warp tile, BKT=64 --------------
// B given as [N,K] hi/lo fp16 scaled by 32. NSTG=2 double buffer.
// SPLIT_A adds the Al*Bh pass (GEMM1). Per-output MMA K-order identical to
// the BKT=32 version (each 64-chunk = two 32-sub-chunks processed in order).
template<bool SPLIT_A>
__global__ void __launch_bounds__(256, 1) hgemm_w2_kernel(
    int M, int N, int K,
    const __half* __restrict__ Ah, const __half* __restrict__ Al,
    const __half* __restrict__ Bh, const __half* __restrict__ Bl,
    const float* __restrict__ bias,
    float* __restrict__ Cout)
{
    extern __shared__ char smem[];
    const int BMT = 128, BNT = 256;
    const int A_TILE = BMT * P2;        // 18432
    const int B_TILE = BNT * P2;        // 36864
    const int AL_OFF = A_TILE;
    const int BH_OFF = SPLIT_A ? 2 * A_TILE : A_TILE;
    const int BL_OFF = BH_OFF + B_TILE;
    const int STAGE  = BL_OFF + B_TILE; // 110592 / 92160
    uint32_t sb = smem_u32(smem);

    int tid  = threadIdx.x;
    int wid  = tid >> 5, lane = tid & 31;
    const int bm = blockIdx.y * BMT;
    const int bn = blockIdx.x * BNT;
    const int NIT = K / BKT2;

    auto load_chunk = [&](int chunk, int s) {
        uint32_t st = sb + (uint32_t)s * STAGE;
        int k0 = chunk * BKT2;
        // rows*8 granules / 256 threads
        const int NQ = ((SPLIT_A ? 2 * BMT : BMT) + 2 * BNT) * 8 / 256;
#pragma unroll
        for (int q = 0; q < NQ; q++) {
            int g = tid + (q << 8);
            int r = g >> 3, gran = g & 7;
            if (r < BMT) {
                cp_async16(st + r * P2 + gran * 16,
                           Ah + (size_t)(bm + r) * K + k0 + gran * 8);
            } else if (SPLIT_A && r < 2 * BMT) {
                int ra = r - BMT;
                cp_async16(st + AL_OFF + ra * P2 + gran * 16,
                           Al + (size_t)(bm + ra) * K + k0 + gran * 8);
            } else {
                int rb = r - (SPLIT_A ? 2 * BMT : BMT);
                if (rb < BNT) {
                    cp_async16(st + BH_OFF + rb * P2 + gran * 16,
                               Bh + (size_t)(bn + rb) * K + k0 + gran * 8);
                } else {
                    rb -= BNT;
                    cp_async16(st + BL_OFF + rb * P2 + gran * 16,
                               Bl + (size_t)(bn + rb) * K + k0 + gran * 8);
                }
            }
        }
    };

    float acc[4][8][4];
#pragma unroll
    for (int i = 0; i < 4; i++)
#pragma unroll
        for (int j = 0; j < 8; j++)
#pragma unroll
            for (int q = 0; q < 4; q++) acc[i][j][q] = 0.f;

    int mw = wid & 1, nw = wid >> 1;     // 2(m) x 4(n)
    uint32_t a_lane = (uint32_t)((mw * 64 + (lane & 15)) * P2 + ((lane >> 4) << 4));
    uint32_t b_lane = (uint32_t)((nw * 64 + (lane & 7)) * P2 + ((lane >> 3) << 4));

    // prologue: stage 0
    load_chunk(0, 0);
    asm volatile("cp.async.commit_group;");

    for (int it = 0; it < NIT; it++) {
        if (it + 1 < NIT) load_chunk(it + 1, (it + 1) & 1);
        asm volatile("cp.async.commit_group;");
        asm volatile("cp.async.wait_group 1;");
        __syncthreads();

        uint32_t st = sb + (uint32_t)(it & 1) * STAGE;

        // two 32-wide sub-chunks, processed in K order
#pragma unroll
        for (int kk = 0; kk < 2; kk++) {
            uint32_t koff = (uint32_t)(kk * 64);   // bytes

            uint32_t a[4][2][4];
#pragma unroll
            for (int i = 0; i < 4; i++)
#pragma unroll
                for (int s = 0; s < 2; s++)
                    ldmx4(a[i][s], st + a_lane + koff + (uint32_t)(i * 16 * P2 + s * 32));

            uint32_t al[SPLIT_A ? 4 : 1][2][4];
            if (SPLIT_A) {
#pragma unroll
                for (int i = 0; i < 4; i++)
#pragma unroll
                    for (int s = 0; s < 2; s++)
                        ldmx4(al[i][s], st + AL_OFF + a_lane + koff +
                                        (uint32_t)(i * 16 * P2 + s * 32));
            }

#pragma unroll
            for (int jg = 0; jg < 8; jg += 2) {
                uint32_t bh[2][4], bl[2][4];
#pragma unroll
                for (int jj = 0; jj < 2; jj++)
                    ldmx4(bh[jj], st + BH_OFF + b_lane + koff +
                                  (uint32_t)((jg + jj) * 8 * P2));
#pragma unroll
                for (int jj = 0; jj < 2; jj++)
                    ldmx4(bl[jj], st + BL_OFF + b_lane + koff +
                                  (uint32_t)((jg + jj) * 8 * P2));
#pragma unroll
                for (int i = 0; i < 4; i++)
#pragma unroll
                    for (int jj = 0; jj < 2; jj++) {
                        float* c = acc[i][jg + jj];
                        mma16816(c, a[i][0], bh[jj][0], bh[jj][1]);
                        mma16816(c, a[i][1], bh[jj][2], bh[jj][3]);
                        mma16816(c, a[i][0], bl[jj][0], bl[jj][1]);
                        mma16816(c, a[i][1], bl[jj][2], bl[jj][3]);
                    }
                if (SPLIT_A) {
#pragma unroll
                    for (int i = 0; i < 4; i++)
#pragma unroll
                        for (int jj = 0; jj < 2; jj++) {
                            float* c = acc[i][jg + jj];
                            mma16816(c, al[i][0], bh[jj][0], bh[jj][1]);
                            mma16816(c, al[i][1], bh[jj][2], bh[jj][3]);
                        }
                }
            }
        }
        __syncthreads();
    }

    // epilogue: cur = acc/32 + bias
    int rg = lane >> 2;
    int cq = (lane & 3) * 2;
#pragma unroll
    for (int i = 0; i < 4; i++) {
#pragma unroll
        for (int j = 0; j < 8; j++) {
            int cn = bn + nw * 64 + j * 8 + cq;
            float bs0 = bias[cn], bs1 = bias[cn + 1];
#pragma unroll
            for (int h = 0; h < 2; h++) {
                int rm = bm + mw * 64 + i * 16 + rg + h * 8;
                float cur0 = acc[i][j][2 * h + 0] * INV_SW + bs0;
                float cur1 = acc[i][j][2 * h + 1] * INV_SW + bs1;
                *(float2*)(Cout + (size_t)rm * N + cn) = make_float2(cur0, cur1);
            }
        }
    }
}

// ------------------------- LIF scan over timesteps --------------------------
// cur [T, MS, NF] fp32 -> spikes (half), membrane in registers across t.
__global__ void lif_scan_kernel(const float* __restrict__ cur,
                                __half* __restrict__ spk, int NF,
                                const float* __restrict__ betas, int bidx,
                                const float* __restrict__ thrs,  int tidx) {
    size_t e = ((size_t)blockIdx.x * blockDim.x + threadIdx.x) * 4;
    float beta = clamp01(betas[bidx]);
    float thr  = thrs[tidx];
    float m0 = 0.f, m1 = 0.f, m2 = 0.f, m3 = 0.f;
    size_t step = (size_t)MS * NF;
#pragma unroll
    for (int t = 0; t < T_STEPS; t++) {
        float4 c = *(const float4*)(cur + t * step + e);
        float mn0 = beta * m0 + c.x - (m0 > thr ? thr : 0.f);
        float mn1 = beta * m1 + c.y - (m1 > thr ? thr : 0.f);
        float mn2 = beta * m2 + c.z - (m2 > thr ? thr : 0.f);
        float mn3 = beta * m3 + c.w - (m3 > thr ? thr : 0.f);
        float sp0 = (mn0 - thr) > 0.f ? 1.f : 0.f;
        float sp1 = (mn1 - thr) > 0.f ? 1.f : 0.f;
        float sp2 = (mn2 - thr) > 0.f ? 1.f : 0.f;
        float sp3 = (mn3 - thr) > 0.f ? 1.f : 0.f;
        __half2* hp = (__half2*)(spk + t * step + e);
        hp[0] = __floats2half2_rn(sp0, sp1);
        hp[1] = __floats2half2_rn(sp2, sp3);
        m0 = mn0; m1 = mn1; m2 = mn2; m3 = mn3;
    }
}

// ---------------------- readout matvec (parallel over t,b) ------------------
__global__ void out_matvec_kernel(const float* __restrict__ Wout,
                                  const float* __restrict__ bout) {
    __shared__ float red[4][256];
    int tb = blockIdx.x;           // t * BB + b
    int t = tb / BB, b = tb % BB;
    int tid = threadIdx.x;
    const __half* s = g_spk2_h + ((size_t)t * MS + b * RR) * H2F;
    const float4* W4 = (const float4*)Wout;
    float a0 = 0.f, a1 = 0.f, a2 = 0.f, a3 = 0.f;
    for (int k = tid; k < FOUT; k += 256) {
        float sv = __half2float(s[k]);
        float4 w = W4[k];
        a0 += sv * w.x; a1 += sv * w.y; a2 += sv * w.z; a3 += sv * w.w;
    }
    red[0][tid] = a0; red[1][tid] = a1; red[2][tid] = a2; red[3][tid] = a3;
    __syncthreads();
    for (int off = 128; off > 0; off >>= 1) {
        if (tid < off) {
#pragma unroll
            for (int q = 0; q < 4; q++) red[q][tid] += red[q][tid + off];
        }
        __syncthreads();
    }
    if (tid < 4)
        g_curout[(t * BB + b) * NCLS + tid] = red[tid][0] + bout[tid];
}

// ---------------------------- output LIF scan -------------------------------
__global__ void out_scan_kernel(const float* __restrict__ betas,
                                float* __restrict__ out) {
    int b = threadIdx.x;           // 32 threads
    float beta = clamp01(betas[3]);
    float m[4] = {0.f, 0.f, 0.f, 0.f};
    for (int t = 0; t < T_STEPS; t++) {
#pragma unroll
        for (int n = 0; n < 4; n++) {
            float cur = g_curout[(t * BB + b) * NCLS + n];
            float mn = beta * m[n] + cur - (m[n] > 1.0f ? 1.0f : 0.f);
            m[n] = mn;
            out[t * BB * NCLS + b * NCLS + n] = (mn - 1.0f) > 0.f ? 1.f : 0.f;
        }
    }
}

// ------------------------------- launch -------------------------------------
extern "C" void kernel_launch(void* const* d_in, const int* in_sizes, int n_in,
                              void* d_out, int out_size) {
    const float* x     = (const float*)d_in[0];
    const float* W_in  = (const float*)d_in[1];
    const float* b_in  = (const float*)d_in[2];
    const float* W_h1  = (const float*)d_in[3];
    const float* b_h1  = (const float*)d_in[4];
    const float* W_h2  = (const float*)d_in[5];
    const float* b_h2  = (const float*)d_in[6];
    const float* W_out = (const float*)d_in[7];
    const float* b_out = (const float*)d_in[8];
    const float* betas = (const float*)d_in[9];
    const float* thrs  = (const float*)d_in[10];
    float* out = (float*)d_out;

    __half *p_feat_h, *p_feat_l, *p_spkin, *p_spk1, *p_spk2;
    __half *p_Winh, *p_Winl, *p_Wh1h, *p_Wh1l, *p_Wh2h, *p_Wh2l;
    float *p_cur;
    cudaGetSymbolAddress((void**)&p_feat_h, g_feat_h);
    cudaGetSymbolAddress((void**)&p_feat_l, g_feat_l);
    cudaGetSymbolAddress((void**)&p_cur,    g_cur);
    cudaGetSymbolAddress((void**)&p_spkin,  g_spkin_h);
    cudaGetSymbolAddress((void**)&p_spk1,   g_spk1_h);
    cudaGetSymbolAddress((void**)&p_spk2,   g_spk2_h);
    cudaGetSymbolAddress((void**)&p_Winh,   g_Win_h);
    cudaGetSymbolAddress((void**)&p_Winl,   g_Win_l);
    cudaGetSymbolAddress((void**)&p_Wh1h,   g_Wh1_h);
    cudaGetSymbolAddress((void**)&p_Wh1l,   g_Wh1_l);
    cudaGetSymbolAddress((void**)&p_Wh2h,   g_Wh2_h);
    cudaGetSymbolAddress((void**)&p_Wh2l,   g_Wh2_l);

    const int SMEMS = 2 * (2 * 128 * P2 + 2 * 256 * P2);  // 221184
    const int SMEMW = 2 * (128 * P2 + 2 * 256 * P2);      // 184320
    cudaFuncSetAttribute((const void*)hgemm_w2_kernel<true>,
                         cudaFuncAttributeMaxDynamicSharedMemorySize, SMEMS);
    cudaFuncSetAttribute((const void*)hgemm_w2_kernel<false>,
                         cudaFuncAttributeMaxDynamicSharedMemorySize, SMEMW);

    pool_kernel<<<T_STEPS * BB * CC * TPP, 256>>>(x);                       // 0
    split_tr_kernel<<<dim3(H0F / 32, D_INF / 32), dim3(32, 8)>>>(
        W_in, p_Winh, p_Winl, D_INF, H0F);                                   // 1
    split_tr_kernel<<<dim3(H1F / 32, H0F / 32),  dim3(32, 8)>>>(
        W_h1, p_Wh1h, p_Wh1l, H0F, H1F);                                     // 2

    // GEMM1 (split-A): cur_in = feat @ W_in + b_in   [14336, 2048]
    hgemm_w2_kernel<true><<<dim3(H0F / 256, M_ALL / 128), 256, SMEMS>>>(     // 3
        M_ALL, H0F, D_INF, p_feat_h, p_feat_l, p_Winh, p_Winl, b_in, p_cur);

    lif_scan_kernel<<<(MS * H0F / 4) / 256, 256>>>(
        p_cur, p_spkin, H0F, betas, 0, thrs, 0);

    split_tr_kernel<<<dim3(H2F / 32, H1F / 32),  dim3(32, 8)>>>(
        W_h2, p_Wh2h, p_Wh2l, H1F, H2F);

    // GEMM2: cur1 = spk_in @ W_h1 + b_h1   [14336, 2048]
    hgemm_w2_kernel<false><<<dim3(H1F / 256, M_ALL / 128), 256, SMEMW>>>(
        M_ALL, H1F, H0F, p_spkin, nullptr, p_Wh1h, p_Wh1l, b_h1, p_cur);

    lif_scan_kernel<<<(MS * H1F / 4) / 256, 256>>>(
        p_cur, p_spk1, H1F, betas, 1, thrs, 1);

    // GEMM3: cur2 = spk1 @ W_h2 + b_h2   [14336, 1024]
    hgemm_w2_kernel<false><<<dim3(H2F / 256, M_ALL / 128), 256, SMEMW>>>(
        M_ALL, H2F, H1F, p_spk1, nullptr, p_Wh2h, p_Wh2l, b_h2, p_cur);

    lif_scan_kernel<<<(MS * H2F / 4) / 256, 256>>>(
        p_cur, p_spk2, H2F, betas, 2, thrs, 2);

    out_matvec_kernel<<<T_STEPS * BB, 256>>>(W_out, b_out);
    out_scan_kernel<<<1, BB>>>(betas, out);
}

// round 17
// speedup vs baseline: 1.8530x; 1.0113x over previous
#include <cuda_runtime.h>
#include <cuda_fp16.h>
#include <stdint.h>

// ---------------------------------------------------------------------------
// SNN: pool -> fc_in -> 3x LIF layers -> readout, T=8.
// Split-precision fp16 HMMA, exact for spikes. Time-batched GEMMs.
// R17: slot-major MMA ordering (breaks acc RAW chains; bit-identical per-
// output order) + GEMM1 two-pass al (de-spill: live regs 255 -> ~190).
// ---------------------------------------------------------------------------

#define T_STEPS 8
#define BB      32
#define CC      4
#define CHUNK   29
#define HH      64
#define WW      64
#define TPP     14
#define HP      32
#define WP      32
#define RR      56
#define D_INF   1024
#define H0F     2048
#define H1F     2048
#define H2F     1024
#define NCLS    4
#define MS      (BB*RR)         // 1792
#define M_ALL   (T_STEPS*MS)    // 14336
#define FOUT    (RR*H2F)        // 57344

#define SCALE_W 32.0f
#define INV_SW  (1.0f/32.0f)

#define BKT2  64                 // K elems per chunk
#define P2    144                // bytes per 128B k-row (+16 pad)

// ------------------------- static scratch ----------------------------------
__device__ __half g_feat_h[(size_t)M_ALL * D_INF];
__device__ __half g_feat_l[(size_t)M_ALL * D_INF];
__device__ float  g_cur   [(size_t)M_ALL * H0F];
__device__ __half g_spkin_h[(size_t)M_ALL * H0F];
__device__ __half g_spk1_h [(size_t)M_ALL * H1F];
__device__ __half g_spk2_h [(size_t)M_ALL * H2F];
__device__ float  g_curout [T_STEPS * BB * NCLS];
__device__ __half g_Win_h[(size_t)H0F * D_INF];
__device__ __half g_Win_l[(size_t)H0F * D_INF];
__device__ __half g_Wh1_h[(size_t)H1F * H0F];
__device__ __half g_Wh1_l[(size_t)H1F * H0F];
__device__ __half g_Wh2_h[(size_t)H2F * H1F];
__device__ __half g_Wh2_l[(size_t)H2F * H1F];

__device__ __forceinline__ float clamp01(float v) {
    return fminf(fmaxf(v, 0.0f), 1.0f);
}
__device__ __forceinline__ uint32_t smem_u32(const void* p) {
    uint32_t a;
    asm("{ .reg .u64 t; cvta.to.shared.u64 t, %1; cvt.u32.u64 %0, t; }" : "=r"(a) : "l"(p));
    return a;
}
__device__ __forceinline__ void cp_async16(uint32_t dst, const void* src) {
    asm volatile("cp.async.cg.shared.global [%0], [%1], 16;" :: "r"(dst), "l"(src));
}
__device__ __forceinline__ void ldmx4(uint32_t* r, uint32_t addr) {
    asm volatile("ldmatrix.sync.aligned.m8n8.x4.shared.b16 {%0,%1,%2,%3}, [%4];"
        : "=r"(r[0]), "=r"(r[1]), "=r"(r[2]), "=r"(r[3]) : "r"(addr));
}
__device__ __forceinline__ void mma16816(float* c, const uint32_t* a,
                                         uint32_t b0, uint32_t b1) {
    asm volatile(
        "mma.sync.aligned.m16n8k16.row.col.f32.f16.f16.f32 "
        "{%0,%1,%2,%3}, {%4,%5,%6,%7}, {%8,%9}, {%0,%1,%2,%3};"
        : "+f"(c[0]), "+f"(c[1]), "+f"(c[2]), "+f"(c[3])
        : "r"(a[0]), "r"(a[1]), "r"(a[2]), "r"(a[3]), "r"(b0), "r"(b1));
}

// ------------------------- weight split + transpose -------------------------
__global__ void split_tr_kernel(const float* __restrict__ W,
                                __half* __restrict__ Th, __half* __restrict__ Tl,
                                int K, int N) {
    __shared__ float tile[32][33];
    int n0 = blockIdx.x * 32, k0 = blockIdx.y * 32;
    int tx = threadIdx.x, ty = threadIdx.y;   // 32 x 8
#pragma unroll
    for (int j = 0; j < 32; j += 8)
        tile[ty + j][tx] = W[(size_t)(k0 + ty + j) * N + n0 + tx];
    __syncthreads();
#pragma unroll
    for (int j = 0; j < 32; j += 8) {
        float w = tile[tx][ty + j] * SCALE_W;
        __half hi = __float2half_rn(w);
        __half lo = __float2half_rn(w - __half2float(hi));
        size_t o = (size_t)(n0 + ty + j) * K + k0 + tx;
        Th[o] = hi; Tl[o] = lo;
    }
}

// ------------------------------- avg pool 3d --------------------------------
__global__ void pool_kernel(const float* __restrict__ x) {
    int blk = blockIdx.x;
    int tp = blk % TPP;
    int c  = (blk / TPP) % CC;
    int b  = (blk / (TPP * CC)) % BB;
    int t  =  blk / (TPP * CC * BB);
    int f0 = t * CHUNK + tp * 2;
    const float* xb = x + ((size_t)(b * CC + c) * 232 + f0) * (HH * WW);
    size_t obase = ((size_t)((t * BB + b) * RR + (c * TPP + tp))) * D_INF;
    __half* oh = g_feat_h + obase;
    __half* ol = g_feat_l + obase;
    for (int d = threadIdx.x; d < HP * WP; d += blockDim.x) {
        int hp = d >> 5, wp = d & 31;
        const float* p = xb + (hp * 2) * WW + wp * 2;
        float s = 0.f;
#pragma unroll
        for (int kd = 0; kd < 3; kd++) {
            const float* pf = p + kd * (HH * WW);
            float2 a0 = *(const float2*)pf;
            float2 a1 = *(const float2*)(pf + WW);
            s += (a0.x + a0.y) + (a1.x + a1.y);
        }
        float v = s / 12.0f;
        __half hi = __float2half_rn(v);
        __half lo = __float2half_rn(v - __half2float(hi));
        oh[d] = hi; ol[d] = lo;
    }
}

// ------------- HMMA GEMM: 128x256 CTA, 64x64 warp tile, BKT=64 --------------
// B given as [N,K] hi/lo fp16 scaled by 32. NSTG=2 double buffer.
// Slot-major MMA ordering inside jg groups; SPLIT_A adds a second j-pass
// (al*Bh with reloaded bh frags). Per-output MMA K-order is bit-identical
// to R16: a.bh01, a.bh23, a.bl01, a.bl23 (, al.bh01, al.bh23) per sub-chunk.
template<bool SPLIT_A>
__global__ void __launch_bounds__(256, 1) hgemm_w2_kernel(
    int M, int N, int K,
    const __half* __restrict__ Ah, const __half* __restrict__ Al,
    const __half* __restrict__ Bh, const __half* __restrict__ Bl,
    const float* __restrict__ bias,
    float* __restrict__ Cout)
{
    extern __shared__ char smem[];
    const int BMT = 128, BNT = 256;
    const int A_TILE = BMT * P2;        // 18432
    const int B_TILE = BNT * P2;        // 36864
    const int AL_OFF = A_TILE;
    const int BH_OFF = SPLIT_A ? 2 * A_TILE : A_TILE;
    const int BL_OFF = BH_OFF + B_TILE;
    const int STAGE  = BL_OFF + B_TILE; // 110592 / 92160
    uint32_t sb = smem_u32(smem);

    int tid  = threadIdx.x;
    int wid  = tid >> 5, lane = tid & 31;
    const int bm = blockIdx.y * BMT;
    const int bn = blockIdx.x * BNT;
    const int NIT = K / BKT2;

    auto load_chunk = [&](int chunk, int s) {
        uint32_t st = sb + (uint32_t)s * STAGE;
        int k0 = chunk * BKT2;
        const int NQ = ((SPLIT_A ? 2 * BMT : BMT) + 2 * BNT) * 8 / 256;
#pragma unroll
        for (int q = 0; q < NQ; q++) {
            int g = tid + (q << 8);
            int r = g >> 3, gran = g & 7;
            if (r < BMT) {
                cp_async16(st + r * P2 + gran * 16,
                           Ah + (size_t)(bm + r) * K + k0 + gran * 8);
            } else if (SPLIT_A && r < 2 * BMT) {
                int ra = r - BMT;
                cp_async16(st + AL_OFF + ra * P2 + gran * 16,
                           Al + (size_t)(bm + ra) * K + k0 + gran * 8);
            } else {
                int rb = r - (SPLIT_A ? 2 * BMT : BMT);
                if (rb < BNT) {
                    cp_async16(st + BH_OFF + rb * P2 + gran * 16,
                               Bh + (size_t)(bn + rb) * K + k0 + gran * 8);
                } else {
                    rb -= BNT;
                    cp_async16(st + BL_OFF + rb * P2 + gran * 16,
                               Bl + (size_t)(bn + rb) * K + k0 + gran * 8);
                }
            }
        }
    };

    float acc[4][8][4];
#pragma unroll
    for (int i = 0; i < 4; i++)
#pragma unroll
        for (int j = 0; j < 8; j++)
#pragma unroll
            for (int q = 0; q < 4; q++) acc[i][j][q] = 0.f;

    int mw = wid & 1, nw = wid >> 1;     // 2(m) x 4(n)
    uint32_t a_lane = (uint32_t)((mw * 64 + (lane & 15)) * P2 + ((lane >> 4) << 4));
    uint32_t b_lane = (uint32_t)((nw * 64 + (lane & 7)) * P2 + ((lane >> 3) << 4));

    load_chunk(0, 0);
    asm volatile("cp.async.commit_group;");

    for (int it = 0; it < NIT; it++) {
        if (it + 1 < NIT) load_chunk(it + 1, (it + 1) & 1);
        asm volatile("cp.async.commit_group;");
        asm volatile("cp.async.wait_group 1;");
        __syncthreads();

        uint32_t st = sb + (uint32_t)(it & 1) * STAGE;

#pragma unroll
        for (int kk = 0; kk < 2; kk++) {
            uint32_t koff = (uint32_t)(kk * 64);   // bytes

            uint32_t a[4][2][4];
#pragma unroll
            for (int i = 0; i < 4; i++)
#pragma unroll
                for (int s = 0; s < 2; s++)
                    ldmx4(a[i][s], st + a_lane + koff + (uint32_t)(i * 16 * P2 + s * 32));

            // pass 1: Ah*Bh + Ah*Bl, slot-major within each jg group
#pragma unroll
            for (int jg = 0; jg < 8; jg += 2) {
                uint32_t bh[2][4], bl[2][4];
#pragma unroll
                for (int jj = 0; jj < 2; jj++)
                    ldmx4(bh[jj], st + BH_OFF + b_lane + koff +
                                  (uint32_t)((jg + jj) * 8 * P2));
#pragma unroll
                for (int jj = 0; jj < 2; jj++)
                    ldmx4(bl[jj], st + BL_OFF + b_lane + koff +
                                  (uint32_t)((jg + jj) * 8 * P2));
                // slot 1: a0 * bh01
#pragma unroll
                for (int i = 0; i < 4; i++)
#pragma unroll
                    for (int jj = 0; jj < 2; jj++)
                        mma16816(acc[i][jg + jj], a[i][0], bh[jj][0], bh[jj][1]);
                // slot 2: a1 * bh23
#pragma unroll
                for (int i = 0; i < 4; i++)
#pragma unroll
                    for (int jj = 0; jj < 2; jj++)
                        mma16816(acc[i][jg + jj], a[i][1], bh[jj][2], bh[jj][3]);
                // slot 3: a0 * bl01
#pragma unroll
                for (int i = 0; i < 4; i++)
#pragma unroll
                    for (int jj = 0; jj < 2; jj++)
                        mma16816(acc[i][jg + jj], a[i][0], bl[jj][0], bl[jj][1]);
                // slot 4: a1 * bl23
#pragma unroll
                for (int i = 0; i < 4; i++)
#pragma unroll
                    for (int jj = 0; jj < 2; jj++)
                        mma16816(acc[i][jg + jj], a[i][1], bl[jj][2], bl[jj][3]);
            }

            // pass 2 (split-A only): Al*Bh with reloaded bh frags
            if (SPLIT_A) {
                uint32_t al[4][2][4];
#pragma unroll
                for (int i = 0; i < 4; i++)
#pragma unroll
                    for (int s = 0; s < 2; s++)
                        ldmx4(al[i][s], st + AL_OFF + a_lane + koff +
                                        (uint32_t)(i * 16 * P2 + s * 32));
#pragma unroll
                for (int jg = 0; jg < 8; jg += 2) {
                    uint32_t bh2[2][4];
#pragma unroll
                    for (int jj = 0; jj < 2; jj++)
                        ldmx4(bh2[jj], st + BH_OFF + b_lane + koff +
                                       (uint32_t)((jg + jj) * 8 * P2));
#pragma unroll
                    for (int i = 0; i < 4; i++)
#pragma unroll
                        for (int jj = 0; jj < 2; jj++)
                            mma16816(acc[i][jg + jj], al[i][0], bh2[jj][0], bh2[jj][1]);
#pragma unroll
                    for (int i = 0; i < 4; i++)
#pragma unroll
                        for (int jj = 0; jj < 2; jj++)
                            mma16816(acc[i][jg + jj], al[i][1], bh2[jj][2], bh2[jj][3]);
                }
            }
        }
        __syncthreads();
    }

    // epilogue: cur = acc/32 + bias
    int rg = lane >> 2;
    int cq = (lane & 3) * 2;
#pragma unroll
    for (int i = 0; i < 4; i++) {
#pragma unroll
        for (int j = 0; j < 8; j++) {
            int cn = bn + nw * 64 + j * 8 + cq;
            float bs0 = bias[cn], bs1 = bias[cn + 1];
#pragma unroll
            for (int h = 0; h < 2; h++) {
                int rm = bm + mw * 64 + i * 16 + rg + h * 8;
                float cur0 = acc[i][j][2 * h + 0] * INV_SW + bs0;
                float cur1 = acc[i][j][2 * h + 1] * INV_SW + bs1;
                *(float2*)(Cout + (size_t)rm * N + cn) = make_float2(cur0, cur1);
            }
        }
    }
}

// ------------------------- LIF scan over timesteps --------------------------
__global__ void lif_scan_kernel(const float* __restrict__ cur,
                                __half* __restrict__ spk, int NF,
                                const float* __restrict__ betas, int bidx,
                                const float* __restrict__ thrs,  int tidx) {
    size_t e = ((size_t)blockIdx.x * blockDim.x + threadIdx.x) * 4;
    float beta = clamp01(betas[bidx]);
    float thr  = thrs[tidx];
    float m0 = 0.f, m1 = 0.f, m2 = 0.f, m3 = 0.f;
    size_t step = (size_t)MS * NF;
#pragma unroll
    for (int t = 0; t < T_STEPS; t++) {
        float4 c = *(const float4*)(cur + t * step + e);
        float mn0 = beta * m0 + c.x - (m0 > thr ? thr : 0.f);
        float mn1 = beta * m1 + c.y - (m1 > thr ? thr : 0.f);
        float mn2 = beta * m2 + c.z - (m2 > thr ? thr : 0.f);
        float mn3 = beta * m3 + c.w - (m3 > thr ? thr : 0.f);
        float sp0 = (mn0 - thr) > 0.f ? 1.f : 0.f;
        float sp1 = (mn1 - thr) > 0.f ? 1.f : 0.f;
        float sp2 = (mn2 - thr) > 0.f ? 1.f : 0.f;
        float sp3 = (mn3 - thr) > 0.f ? 1.f : 0.f;
        __half2* hp = (__half2*)(spk + t * step + e);
        hp[0] = __floats2half2_rn(sp0, sp1);
        hp[1] = __floats2half2_rn(sp2, sp3);
        m0 = mn0; m1 = mn1; m2 = mn2; m3 = mn3;
    }
}

// ---------------------- readout matvec (parallel over t,b) ------------------
__global__ void out_matvec_kernel(const float* __restrict__ Wout,
                                  const float* __restrict__ bout) {
    __shared__ float red[4][256];
    int tb = blockIdx.x;
    int t = tb / BB, b = tb % BB;
    int tid = threadIdx.x;
    const __half* s = g_spk2_h + ((size_t)t * MS + b * RR) * H2F;
    const float4* W4 = (const float4*)Wout;
    float a0 = 0.f, a1 = 0.f, a2 = 0.f, a3 = 0.f;
    for (int k = tid; k < FOUT; k += 256) {
        float sv = __half2float(s[k]);
        float4 w = W4[k];
        a0 += sv * w.x; a1 += sv * w.y; a2 += sv * w.z; a3 += sv * w.w;
    }
    red[0][tid] = a0; red[1][tid] = a1; red[2][tid] = a2; red[3][tid] = a3;
    __syncthreads();
    for (int off = 128; off > 0; off >>= 1) {
        if (tid < off) {
#pragma unroll
            for (int q = 0; q < 4; q++) red[q][tid] += red[q][tid + off];
        }
        __syncthreads();
    }
    if (tid < 4)
        g_curout[(t * BB + b) * NCLS + tid] = red[tid][0] + bout[tid];
}

// ---------------------------- output LIF scan -------------------------------
__global__ void out_scan_kernel(const float* __restrict__ betas,
                                float* __restrict__ out) {
    int b = threadIdx.x;
    float beta = clamp01(betas[3]);
    float m[4] = {0.f, 0.f, 0.f, 0.f};
    for (int t = 0; t < T_STEPS; t++) {
#pragma unroll
        for (int n = 0; n < 4; n++) {
            float cur = g_curout[(t * BB + b) * NCLS + n];
            float mn = beta * m[n] + cur - (m[n] > 1.0f ? 1.0f : 0.f);
            m[n] = mn;
            out[t * BB * NCLS + b * NCLS + n] = (mn - 1.0f) > 0.f ? 1.f : 0.f;
        }
    }
}

// ------------------------------- launch -------------------------------------
extern "C" void kernel_launch(void* const* d_in, const int* in_sizes, int n_in,
                              void* d_out, int out_size) {
    const float* x     = (const float*)d_in[0];
    const float* W_in  = (const float*)d_in[1];
    const float* b_in  = (const float*)d_in[2];
    const float* W_h1  = (const float*)d_in[3];
    const float* b_h1  = (const float*)d_in[4];
    const float* W_h2  = (const float*)d_in[5];
    const float* b_h2  = (const float*)d_in[6];
    const float* W_out = (const float*)d_in[7];
    const float* b_out = (const float*)d_in[8];
    const float* betas = (const float*)d_in[9];
    const float* thrs  = (const float*)d_in[10];
    float* out = (float*)d_out;

    __half *p_feat_h, *p_feat_l, *p_spkin, *p_spk1, *p_spk2;
    __half *p_Winh, *p_Winl, *p_Wh1h, *p_Wh1l, *p_Wh2h, *p_Wh2l;
    float *p_cur;
    cudaGetSymbolAddress((void**)&p_feat_h, g_feat_h);
    cudaGetSymbolAddress((void**)&p_feat_l, g_feat_l);
    cudaGetSymbolAddress((void**)&p_cur,    g_cur);
    cudaGetSymbolAddress((void**)&p_spkin,  g_spkin_h);
    cudaGetSymbolAddress((void**)&p_spk1,   g_spk1_h);
    cudaGetSymbolAddress((void**)&p_spk2,   g_spk2_h);
    cudaGetSymbolAddress((void**)&p_Winh,   g_Win_h);
    cudaGetSymbolAddress((void**)&p_Winl,   g_Win_l);
    cudaGetSymbolAddress((void**)&p_Wh1h,   g_Wh1_h);
    cudaGetSymbolAddress((void**)&p_Wh1l,   g_Wh1_l);
    cudaGetSymbolAddress((void**)&p_Wh2h,   g_Wh2_h);
    cudaGetSymbolAddress((void**)&p_Wh2l,   g_Wh2_l);

    const int SMEMS = 2 * (2 * 128 * P2 + 2 * 256 * P2);  // 221184
    const int SMEMW = 2 * (128 * P2 + 2 * 256 * P2);      // 184320
    cudaFuncSetAttribute((const void*)hgemm_w2_kernel<true>,
                         cudaFuncAttributeMaxDynamicSharedMemorySize, SMEMS);
    cudaFuncSetAttribute((const void*)hgemm_w2_kernel<false>,
                         cudaFuncAttributeMaxDynamicSharedMemorySize, SMEMW);

    pool_kernel<<<T_STEPS * BB * CC * TPP, 256>>>(x);                       // 0
    split_tr_kernel<<<dim3(H0F / 32, D_INF / 32), dim3(32, 8)>>>(
        W_in, p_Winh, p_Winl, D_INF, H0F);                                   // 1
    split_tr_kernel<<<dim3(H1F / 32, H0F / 32),  dim3(32, 8)>>>(
        W_h1, p_Wh1h, p_Wh1l, H0F, H1F);                                     // 2

    // GEMM1 (split-A): cur_in = feat @ W_in + b_in   [14336, 2048]
    hgemm_w2_kernel<true><<<dim3(H0F / 256, M_ALL / 128), 256, SMEMS>>>(     // 3
        M_ALL, H0F, D_INF, p_feat_h, p_feat_l, p_Winh, p_Winl, b_in, p_cur);

    lif_scan_kernel<<<(MS * H0F / 4) / 256, 256>>>(
        p_cur, p_spkin, H0F, betas, 0, thrs, 0);

    split_tr_kernel<<<dim3(H2F / 32, H1F / 32),  dim3(32, 8)>>>(
        W_h2, p_Wh2h, p_Wh2l, H1F, H2F);

    // GEMM2: cur1 = spk_in @ W_h1 + b_h1   [14336, 2048]
    hgemm_w2_kernel<false><<<dim3(H1F / 256, M_ALL / 128), 256, SMEMW>>>(
        M_ALL, H1F, H0F, p_spkin, nullptr, p_Wh1h, p_Wh1l, b_h1, p_cur);

    lif_scan_kernel<<<(MS * H1F / 4) / 256, 256>>>(
        p_cur, p_spk1, H1F, betas, 1, thrs, 1);

    // GEMM3: cur2 = spk1 @ W_h2 + b_h2   [14336, 1024]
    hgemm_w2_kernel<false><<<dim3(H2F / 256, M_ALL / 128), 256, SMEMW>>>(
        M_ALL, H2F, H1F, p_spk1, nullptr, p_Wh2h, p_Wh2l, b_h2, p_cur);

    lif_scan_kernel<<<(MS * H2F / 4) / 256, 256>>>(
        p_cur, p_spk2, H2F, betas, 2, thrs, 2);

    out_matvec_kernel<<<T_STEPS * BB, 256>>>(W_out, b_out);
    out_scan_kernel<<<1, BB>>>(betas, out);
}